// round 12
// baseline (speedup 1.0000x reference)
#include <cuda_runtime.h>
#include <cuda_bf16.h>

// ---------------- problem constants ----------------
#define Bc    16
#define NNc   2000
#define Nc    (Bc * NNc)        // 32000 nodes
#define FINc  128
#define Hc    4
#define Cc    64
#define HCc   256
#define EMAXT 480000
#define FCINc (6 * NNc)         // 12000
#define F1c   512
#define F2c   128
#define FC1KT 16
#define FC2KT 4

// output layout (flattened tuple: pred, x0, x1, x2, ms)
#define OFF_PRED 0
#define OFF_X0   16
#define OFF_X1   (OFF_X0 + Bc * NNc)
#define OFF_X2   (OFF_X1 + Bc * NNc)
#define OFF_MS   (OFF_X2 + Bc * NNc)

// ---------------- device scratch ----------------
__device__ float g_hin[Nc * HCc];
__device__ float g_h[Nc * HCc];
__device__ float g_as[Nc * Hc];
__device__ float g_ad[Nc * Hc];
__device__ float g_wax[HCc * 8];
__device__ int   g_cnt[Nc];
__device__ int   g_rowp[Nc + 1];
__device__ int   g_cur[Nc];
__device__ int   g_csrc[EMAXT];
__device__ float g_x[3 * Bc * NNc];
__device__ float g_t[Bc * FCINc];
__device__ float g_fc1[Bc * F1c];
__device__ float g_fc2[Bc * F2c];

// ---------------- bf16 split helpers ----------------
__device__ __forceinline__ void bsplit2(float x0, float x1,
                                        unsigned& h, unsigned& l) {
    const __nv_bfloat16 h0 = __float2bfloat16(x0);
    const __nv_bfloat16 h1 = __float2bfloat16(x1);
    const __nv_bfloat16 l0 = __float2bfloat16(x0 - __bfloat162float(h0));
    const __nv_bfloat16 l1 = __float2bfloat16(x1 - __bfloat162float(h1));
    h = (unsigned)__bfloat16_as_ushort(h0) |
        ((unsigned)__bfloat16_as_ushort(h1) << 16);
    l = (unsigned)__bfloat16_as_ushort(l0) |
        ((unsigned)__bfloat16_as_ushort(l1) << 16);
}

__device__ __forceinline__ void mma16(float* d,
                                      unsigned a0, unsigned a1,
                                      unsigned a2, unsigned a3,
                                      unsigned b0, unsigned b1) {
    asm volatile(
        "mma.sync.aligned.m16n8k16.row.col.f32.bf16.bf16.f32 "
        "{%0,%1,%2,%3}, {%4,%5,%6,%7}, {%8,%9}, {%0,%1,%2,%3};"
        : "+f"(d[0]), "+f"(d[1]), "+f"(d[2]), "+f"(d[3])
        : "r"(a0), "r"(a1), "r"(a2), "r"(a3), "r"(b0), "r"(b1));
}

// ---------------- CSR build ----------------
__global__ void zero_cnt_kernel() {
    const int i = blockIdx.x * blockDim.x + threadIdx.x;
    if (i < Nc) g_cnt[i] = 0;
}

__global__ void csr_count_kernel(const int* __restrict__ ei, int Eb, int Et) {
    const int e = blockIdx.x * blockDim.x + threadIdx.x;
    if (e >= Et) return;
    const int d = (e < Eb) ? ei[Eb + e] : (e - Eb);
    atomicAdd(&g_cnt[d], 1);
}

__global__ void scan_kernel() {
    __shared__ int partial[1024];
    const int T = 1024, CH = (Nc + T - 1) / T;
    const int t = threadIdx.x;
    const int base = t * CH;
    int s = 0;
    for (int i = 0; i < CH; ++i) {
        const int idx = base + i;
        if (idx < Nc) s += g_cnt[idx];
    }
    partial[t] = s;
    __syncthreads();
    for (int off = 1; off < T; off <<= 1) {
        int v = (t >= off) ? partial[t - off] : 0;
        __syncthreads();
        partial[t] += v;
        __syncthreads();
    }
    int run = t ? partial[t - 1] : 0;
    for (int i = 0; i < CH; ++i) {
        const int idx = base + i;
        if (idx < Nc) {
            g_rowp[idx] = run;
            g_cur[idx]  = run;
            run += g_cnt[idx];
        }
    }
    if (t == T - 1) g_rowp[Nc] = run;
}

__global__ void csr_fill_kernel(const int* __restrict__ ei, int Eb, int Et) {
    const int e = blockIdx.x * blockDim.x + threadIdx.x;
    if (e >= Et) return;
    int s, d;
    if (e < Eb) { s = ei[e]; d = ei[Eb + e]; }
    else        { s = e - Eb; d = s; }
    const int p = atomicAdd(&g_cur[d], 1);
    g_csrc[p] = s;
}

// ---------------- WA = W @ att ----------------
template <int K>
__global__ void wa_kernel(const float* __restrict__ W,
                          const float* __restrict__ attS,
                          const float* __restrict__ attD) {
    const int t = blockIdx.x * blockDim.x + threadIdx.x;
    if (t >= K * Hc) return;
    const int k = t >> 2, h = t & 3;
    float ss = 0.f, dd = 0.f;
#pragma unroll 8
    for (int c = 0; c < Cc; ++c) {
        const float w = W[k * HCc + h * Cc + c];
        ss = fmaf(w, attS[h * Cc + c], ss);
        dd = fmaf(w, attD[h * Cc + c], dd);
    }
    g_wax[k * 8 + h]     = ss;
    g_wax[k * 8 + 4 + h] = dd;
}

// ---------------- attention logits: a[n][hh] = x[n] . WA[:,hh] -------------
// use_gh selects g_h INSIDE the kernel (never pass a __device__ symbol from
// host — GB300 ATS silently dereferences the host shadow and reads zeros).
template <int K>
__global__ void __launch_bounds__(256)
att_logits_kernel(const float* __restrict__ X, int use_gh) {
    __shared__ float swa[8 * K];  // transposed: [c][k]
    const int j = threadIdx.x;
    const float* Xr = use_gh ? g_h : X;
    for (int i = j; i < K * 8; i += 256) {
        const int k = i >> 3, c = i & 7;
        swa[c * K + k] = g_wax[i];
    }
    __syncthreads();
    const int wip = j >> 5, lane = j & 31;
    const int n = blockIdx.x * 8 + wip;
    const float* xr = Xr + (size_t)n * K;
    float acc[8];
#pragma unroll
    for (int c = 0; c < 8; ++c) acc[c] = 0.f;
    for (int k = lane; k < K; k += 32) {
        const float xv = xr[k];
#pragma unroll
        for (int c = 0; c < 8; ++c)
            acc[c] = fmaf(xv, swa[c * K + k], acc[c]);
    }
#pragma unroll
    for (int o = 16; o; o >>= 1) {
#pragma unroll
        for (int c = 0; c < 8; ++c)
            acc[c] += __shfl_xor_sync(0xffffffffu, acc[c], o);
    }
    if (!lane) {
        *reinterpret_cast<float4*>(&g_as[n * Hc]) =
            make_float4(acc[0], acc[1], acc[2], acc[3]);
        *reinterpret_cast<float4*>(&g_ad[n * Hc]) =
            make_float4(acc[4], acc[5], acc[6], acc[7]);
    }
}

// ---------------- tensor-core node GEMM: hin = X @ W (bf16 3-term split) ---
// R10 fragment layout. X split ONCE into dynamic smem for the full K range;
// block loops over 2 column tiles (grid.y = HCc/128), halving X LDG+STS.
template <int K>
__global__ void __launch_bounds__(256)
gemm_tc_kernel(const float* __restrict__ X, const float* __restrict__ W,
               int use_gh) {
    extern __shared__ unsigned smemb[];
    const int K2 = K / 2, K2P = K2 + 1;
    unsigned* xhi = smemb;                 // [64][K2P]
    unsigned* xlo = xhi + 64 * K2P;        // [64][K2P]
    unsigned* wh  = xlo + 64 * K2P;        // [64][17]
    unsigned* wl  = wh + 64 * 17;          // [64][17]

    const float* Xr = use_gh ? g_h : X;
    const int n0 = blockIdx.x * 64;
    const int tid = threadIdx.x;
    const int warp = tid >> 5, lane = tid & 31;
    const int g = lane >> 2, t4 = lane & 3;
    const int rw = (warp & 3) * 16;
    const int cw = (warp >> 2) * 32;

    // phase 1: load + split the full 64 x K X tile once
    for (int idx = tid; idx < 64 * (K / 4); idx += 256) {
        const int r = idx / (K / 4), q = idx % (K / 4);
        const float4 v = *reinterpret_cast<const float4*>(
            &Xr[(size_t)(n0 + r) * K + q * 4]);
        bsplit2(v.x, v.y, xhi[r * K2P + q * 2],     xlo[r * K2P + q * 2]);
        bsplit2(v.z, v.w, xhi[r * K2P + q * 2 + 1], xlo[r * K2P + q * 2 + 1]);
    }
    __syncthreads();

    // phase 2: two 64-col output tiles reuse the same X
    for (int ct = 0; ct < 2; ++ct) {
        const int c0 = blockIdx.y * 128 + ct * 64;

        float d[4][4];
#pragma unroll
        for (int t = 0; t < 4; ++t)
#pragma unroll
            for (int i = 0; i < 4; ++i) d[t][i] = 0.f;

        for (int kc = 0; kc < K; kc += 32) {
            // W tile 32x64 -> transposed packed: thread = (k2, n4)
            {
                const int k2 = tid >> 4, n4 = tid & 15;
                const float* wp = &W[(size_t)(kc + 2 * k2) * HCc + c0 + n4 * 4];
                const float4 v0 = *reinterpret_cast<const float4*>(wp);
                const float4 v1 = *reinterpret_cast<const float4*>(wp + HCc);
                bsplit2(v0.x, v1.x, wh[(n4 * 4 + 0) * 17 + k2], wl[(n4 * 4 + 0) * 17 + k2]);
                bsplit2(v0.y, v1.y, wh[(n4 * 4 + 1) * 17 + k2], wl[(n4 * 4 + 1) * 17 + k2]);
                bsplit2(v0.z, v1.z, wh[(n4 * 4 + 2) * 17 + k2], wl[(n4 * 4 + 2) * 17 + k2]);
                bsplit2(v0.w, v1.w, wh[(n4 * 4 + 3) * 17 + k2], wl[(n4 * 4 + 3) * 17 + k2]);
            }
            __syncthreads();

            const int kb = kc >> 1;
#pragma unroll
            for (int ks2 = 0; ks2 < 16; ks2 += 8) {
                const unsigned* xh0 = &xhi[(rw + g) * K2P + kb + ks2];
                const unsigned* xh1 = &xhi[(rw + g + 8) * K2P + kb + ks2];
                const unsigned* xl0 = &xlo[(rw + g) * K2P + kb + ks2];
                const unsigned* xl1 = &xlo[(rw + g + 8) * K2P + kb + ks2];
                const unsigned a0h = xh0[t4];
                const unsigned a1h = xh1[t4];
                const unsigned a2h = xh0[4 + t4];
                const unsigned a3h = xh1[4 + t4];
                const unsigned a0l = xl0[t4];
                const unsigned a1l = xl1[t4];
                const unsigned a2l = xl0[4 + t4];
                const unsigned a3l = xl1[4 + t4];
#pragma unroll
                for (int t = 0; t < 4; ++t) {
                    const int bn = cw + t * 8 + g;
                    const unsigned b0h = wh[bn * 17 + ks2 + t4];
                    const unsigned b1h = wh[bn * 17 + ks2 + 4 + t4];
                    const unsigned b0l = wl[bn * 17 + ks2 + t4];
                    const unsigned b1l = wl[bn * 17 + ks2 + 4 + t4];
                    mma16(d[t], a0h, a1h, a2h, a3h, b0h, b1h);
                    mma16(d[t], a0h, a1h, a2h, a3h, b0l, b1l);
                    mma16(d[t], a0l, a1l, a2l, a3l, b0h, b1h);
                }
            }
            __syncthreads();
        }

        // store 64x64 tile
        const int r  = n0 + rw + g;
        const int cc = c0 + cw + t4 * 2;
#pragma unroll
        for (int t = 0; t < 4; ++t) {
            *reinterpret_cast<float2*>(&g_hin[(size_t)r * HCc + cc + t * 8]) =
                make_float2(d[t][0], d[t][1]);
            *reinterpret_cast<float2*>(&g_hin[(size_t)(r + 8) * HCc + cc + t * 8]) =
                make_float2(d[t][2], d[t][3]);
        }
    }
}

// ---------------- fused GAT aggregation: warp per dst node ----------------
// Softmax without max-subtraction (logits are O(1); exp() fp32-safe; the
// normalized ratio is mathematically identical). Single-chunk fast path
// (deg <= 32, the common case) computes stats and weights in ONE pass.
__device__ __forceinline__ float leaky02(float a) {
    return a > 0.f ? a : 0.2f * a;
}

__global__ void __launch_bounds__(256)
gat_agg_kernel(const float* __restrict__ bias,
               const float* __restrict__ pw,
               const float* __restrict__ pb,
               int xoff) {
    const int wip  = threadIdx.x >> 5;
    const int lane = threadIdx.x & 31;
    const int n = blockIdx.x * 8 + wip;
    __shared__ float s_w[8][32][4];   // UNNORMALIZED exp weights
    __shared__ int   s_src[8][32];

    const int beg = g_rowp[n], end = g_rowp[n + 1];
    const int deg = end - beg;
    const float4 ad = *reinterpret_cast<const float4*>(&g_ad[n * Hc]);

    float4 sm;
    if (deg <= 32) {
        float4 w = make_float4(0.f, 0.f, 0.f, 0.f);
        if (lane < deg) {
            const int s = g_csrc[beg + lane];
            s_src[wip][lane] = s;
            const float4 as = *reinterpret_cast<const float4*>(&g_as[s * Hc]);
            w.x = __expf(leaky02(as.x + ad.x));
            w.y = __expf(leaky02(as.y + ad.y));
            w.z = __expf(leaky02(as.z + ad.z));
            w.w = __expf(leaky02(as.w + ad.w));
            *reinterpret_cast<float4*>(&s_w[wip][lane][0]) = w;
        }
        sm = w;
#pragma unroll
        for (int o = 16; o; o >>= 1) {
            sm.x += __shfl_xor_sync(0xffffffffu, sm.x, o);
            sm.y += __shfl_xor_sync(0xffffffffu, sm.y, o);
            sm.z += __shfl_xor_sync(0xffffffffu, sm.z, o);
            sm.w += __shfl_xor_sync(0xffffffffu, sm.w, o);
        }
    } else {
        sm = make_float4(0.f, 0.f, 0.f, 0.f);
        for (int e = beg + lane; e < end; e += 32) {
            const int s = g_csrc[e];
            const float4 as = *reinterpret_cast<const float4*>(&g_as[s * Hc]);
            sm.x += __expf(leaky02(as.x + ad.x));
            sm.y += __expf(leaky02(as.y + ad.y));
            sm.z += __expf(leaky02(as.z + ad.z));
            sm.w += __expf(leaky02(as.w + ad.w));
        }
#pragma unroll
        for (int o = 16; o; o >>= 1) {
            sm.x += __shfl_xor_sync(0xffffffffu, sm.x, o);
            sm.y += __shfl_xor_sync(0xffffffffu, sm.y, o);
            sm.z += __shfl_xor_sync(0xffffffffu, sm.z, o);
            sm.w += __shfl_xor_sync(0xffffffffu, sm.w, o);
        }
    }
    const float4 inv = make_float4(1.f / (sm.x + 1e-16f), 1.f / (sm.y + 1e-16f),
                                   1.f / (sm.z + 1e-16f), 1.f / (sm.w + 1e-16f));

    const int h  = lane >> 3;
    const int c0 = lane * 8;
    const float invh = reinterpret_cast<const float*>(&inv)[h];
    float4 acc0 = make_float4(0.f, 0.f, 0.f, 0.f);
    float4 acc1 = make_float4(0.f, 0.f, 0.f, 0.f);

    for (int cb = beg; cb < end; cb += 32) {
        const int ne = min(32, end - cb);
        if (cb != beg || deg > 32) {
            __syncwarp();
            if (lane < ne) {
                const int s = g_csrc[cb + lane];
                s_src[wip][lane] = s;
                const float4 as = *reinterpret_cast<const float4*>(&g_as[s * Hc]);
                float4 w;
                w.x = __expf(leaky02(as.x + ad.x));
                w.y = __expf(leaky02(as.y + ad.y));
                w.z = __expf(leaky02(as.z + ad.z));
                w.w = __expf(leaky02(as.w + ad.w));
                *reinterpret_cast<float4*>(&s_w[wip][lane][0]) = w;
            }
        }
        __syncwarp();
        int e = 0;
#pragma unroll 2
        for (; e + 2 <= ne; e += 2) {
            const int   sA = s_src[wip][e];
            const int   sB = s_src[wip][e + 1];
            const float wA = s_w[wip][e][h] * invh;
            const float wB = s_w[wip][e + 1][h] * invh;
            const float* rowA = &g_hin[(size_t)sA * HCc + c0];
            const float* rowB = &g_hin[(size_t)sB * HCc + c0];
            const float4 a0 = *reinterpret_cast<const float4*>(rowA);
            const float4 a1 = *reinterpret_cast<const float4*>(rowA + 4);
            const float4 b0 = *reinterpret_cast<const float4*>(rowB);
            const float4 b1 = *reinterpret_cast<const float4*>(rowB + 4);
            acc0.x = fmaf(wA, a0.x, acc0.x); acc0.y = fmaf(wA, a0.y, acc0.y);
            acc0.z = fmaf(wA, a0.z, acc0.z); acc0.w = fmaf(wA, a0.w, acc0.w);
            acc1.x = fmaf(wA, a1.x, acc1.x); acc1.y = fmaf(wA, a1.y, acc1.y);
            acc1.z = fmaf(wA, a1.z, acc1.z); acc1.w = fmaf(wA, a1.w, acc1.w);
            acc0.x = fmaf(wB, b0.x, acc0.x); acc0.y = fmaf(wB, b0.y, acc0.y);
            acc0.z = fmaf(wB, b0.z, acc0.z); acc0.w = fmaf(wB, b0.w, acc0.w);
            acc1.x = fmaf(wB, b1.x, acc1.x); acc1.y = fmaf(wB, b1.y, acc1.y);
            acc1.z = fmaf(wB, b1.z, acc1.z); acc1.w = fmaf(wB, b1.w, acc1.w);
        }
        if (e < ne) {
            const int   s = s_src[wip][e];
            const float w = s_w[wip][e][h] * invh;
            const float* row = &g_hin[(size_t)s * HCc + c0];
            const float4 v0 = *reinterpret_cast<const float4*>(row);
            const float4 v1 = *reinterpret_cast<const float4*>(row + 4);
            acc0.x = fmaf(w, v0.x, acc0.x); acc0.y = fmaf(w, v0.y, acc0.y);
            acc0.z = fmaf(w, v0.z, acc0.z); acc0.w = fmaf(w, v0.w, acc0.w);
            acc1.x = fmaf(w, v1.x, acc1.x); acc1.y = fmaf(w, v1.y, acc1.y);
            acc1.z = fmaf(w, v1.z, acc1.z); acc1.w = fmaf(w, v1.w, acc1.w);
        }
    }

    const float4 b0 = *reinterpret_cast<const float4*>(&bias[c0]);
    const float4 b1 = *reinterpret_cast<const float4*>(&bias[c0 + 4]);
    float4 r0, r1;
    r0.x = fmaxf(acc0.x + b0.x, 0.f); r0.y = fmaxf(acc0.y + b0.y, 0.f);
    r0.z = fmaxf(acc0.z + b0.z, 0.f); r0.w = fmaxf(acc0.w + b0.w, 0.f);
    r1.x = fmaxf(acc1.x + b1.x, 0.f); r1.y = fmaxf(acc1.y + b1.y, 0.f);
    r1.z = fmaxf(acc1.z + b1.z, 0.f); r1.w = fmaxf(acc1.w + b1.w, 0.f);
    float* orow = &g_h[(size_t)n * HCc + c0];
    *reinterpret_cast<float4*>(orow)     = r0;
    *reinterpret_cast<float4*>(orow + 4) = r1;

    const float4 p0 = *reinterpret_cast<const float4*>(&pw[c0]);
    const float4 p1 = *reinterpret_cast<const float4*>(&pw[c0 + 4]);
    float p = r0.x * p0.x + r0.y * p0.y + r0.z * p0.z + r0.w * p0.w +
              r1.x * p1.x + r1.y * p1.y + r1.z * p1.z + r1.w * p1.w;
#pragma unroll
    for (int o = 16; o; o >>= 1) p += __shfl_xor_sync(0xffffffffu, p, o);
    if (!lane) g_x[xoff + n] = p + pb[0];
}

// ---------------- misc ----------------
__global__ void x0_mean_kernel(const float* __restrict__ x) {
    const int warp = (blockIdx.x * blockDim.x + threadIdx.x) >> 5;
    const int lane = threadIdx.x & 31;
    if (warp >= Nc) return;
    const float4 v = reinterpret_cast<const float4*>(x + (size_t)warp * FINc)[lane];
    float s = v.x + v.y + v.z + v.w;
    for (int o = 16; o; o >>= 1) s += __shfl_down_sync(0xffffffffu, s, o);
    if (!lane) g_x[warp] = s * (1.0f / FINc);
}

__global__ void ln_kernel(const float* __restrict__ w,
                          const float* __restrict__ b,
                          float* __restrict__ dout) {
    const int a  = blockIdx.x / Bc;
    const int bb = blockIdx.x % Bc;
    const float* src = g_x + a * Bc * NNc + bb * NNc;
    __shared__ float rs[256], rq[256];
    float s = 0.f, q = 0.f;
    for (int i = threadIdx.x; i < NNc; i += 256) {
        const float v = src[i];
        s += v; q += v * v;
    }
    rs[threadIdx.x] = s; rq[threadIdx.x] = q;
    __syncthreads();
    for (int o = 128; o; o >>= 1) {
        if (threadIdx.x < o) {
            rs[threadIdx.x] += rs[threadIdx.x + o];
            rq[threadIdx.x] += rq[threadIdx.x + o];
        }
        __syncthreads();
    }
    const float mu  = rs[0] * (1.0f / NNc);
    const float var = rq[0] * (1.0f / NNc) - mu * mu;
    const float inv = rsqrtf(var + 1e-5f);
    for (int i = threadIdx.x; i < NNc; i += 256) {
        const float y = (src[i] - mu) * inv * w[i] + b[i];
        dout[OFF_X0 + a * Bc * NNc + bb * NNc + i] = y;
        dout[OFF_MS + bb * 3 * NNc + a * NNc + i] = y;
        g_t[bb * FCINc + 3 * NNc + a * NNc + i]   = y;
    }
}

__global__ void demo_kernel(const float* __restrict__ sex_emb,
                            const float* __restrict__ mut_emb,
                            const float* __restrict__ age_w,
                            const float* __restrict__ age_b,
                            const float* __restrict__ age,
                            const int* __restrict__ sex,
                            const int* __restrict__ mut) {
    const int i = blockIdx.x * blockDim.x + threadIdx.x;
    if (i >= Bc * NNc) return;
    const int bb = i / NNc, i2 = i % NNc;
    g_t[bb * FCINc + i2]            = sex_emb[sex[bb] * NNc + i2];
    g_t[bb * FCINc + NNc + i2]      = mut_emb[mut[bb] * NNc + i2];
    g_t[bb * FCINc + 2 * NNc + i2]  = fmaf(age[bb], age_w[i2], age_b[i2]);
}

__global__ void fc1_init_kernel(const float* __restrict__ bias) {
    const int i = blockIdx.x * blockDim.x + threadIdx.x;
    if (i < Bc * F1c) g_fc1[i] = bias[i & (F1c - 1)];
}

__global__ void fc1_kernel(const float* __restrict__ w) {
    __shared__ float ts[FCINc / FC1KT];
    const int bb = blockIdx.x >> 4;
    const int kt = blockIdx.x & (FC1KT - 1);
    const int k0 = kt * (FCINc / FC1KT);
    for (int k = threadIdx.x; k < FCINc / FC1KT; k += 128)
        ts[k] = g_t[bb * FCINc + k0 + k];
    __syncthreads();
    const int j4 = threadIdx.x * 4;
    float4 a0 = make_float4(0, 0, 0, 0), a1 = make_float4(0, 0, 0, 0);
    for (int k = 0; k < FCINc / FC1KT; k += 2) {
        const float t0 = ts[k], t1 = ts[k + 1];
        const float4 w0 = *reinterpret_cast<const float4*>(&w[(size_t)(k0 + k) * F1c + j4]);
        const float4 w1 = *reinterpret_cast<const float4*>(&w[(size_t)(k0 + k + 1) * F1c + j4]);
        a0.x = fmaf(t0, w0.x, a0.x); a1.x = fmaf(t1, w1.x, a1.x);
        a0.y = fmaf(t0, w0.y, a0.y); a1.y = fmaf(t1, w1.y, a1.y);
        a0.z = fmaf(t0, w0.z, a0.z); a1.z = fmaf(t1, w1.z, a1.z);
        a0.w = fmaf(t0, w0.w, a0.w); a1.w = fmaf(t1, w1.w, a1.w);
    }
    atomicAdd(&g_fc1[bb * F1c + j4 + 0], a0.x + a1.x);
    atomicAdd(&g_fc1[bb * F1c + j4 + 1], a0.y + a1.y);
    atomicAdd(&g_fc1[bb * F1c + j4 + 2], a0.z + a1.z);
    atomicAdd(&g_fc1[bb * F1c + j4 + 3], a0.w + a1.w);
}

__global__ void fc2_init_kernel(const float* __restrict__ bias) {
    const int i = blockIdx.x * blockDim.x + threadIdx.x;
    if (i < Bc * F2c) g_fc2[i] = bias[i & (F2c - 1)];
}

__global__ void fc2_kernel(const float* __restrict__ w) {
    __shared__ float ts[F1c / FC2KT];
    const int bb = blockIdx.x >> 2;
    const int kt = blockIdx.x & (FC2KT - 1);
    const int k0 = kt * (F1c / FC2KT);
    for (int k = threadIdx.x; k < F1c / FC2KT; k += 128)
        ts[k] = fmaxf(g_fc1[bb * F1c + k0 + k], 0.f);
    __syncthreads();
    const int j = threadIdx.x;
    float a0 = 0.f, a1 = 0.f;
    for (int k = 0; k < F1c / FC2KT; k += 2) {
        a0 = fmaf(ts[k],     w[(size_t)(k0 + k) * F2c + j],     a0);
        a1 = fmaf(ts[k + 1], w[(size_t)(k0 + k + 1) * F2c + j], a1);
    }
    atomicAdd(&g_fc2[bb * F2c + j], a0 + a1);
}

__global__ void fc3_kernel(const float* __restrict__ w,
                           const float* __restrict__ bias,
                           float* __restrict__ dout) {
    const int bb = threadIdx.x >> 5;
    const int lane = threadIdx.x & 31;
    float acc = 0.f;
    for (int k = lane; k < F2c; k += 32)
        acc += fmaxf(g_fc2[bb * F2c + k], 0.f) * w[k];
    for (int o = 16; o; o >>= 1) acc += __shfl_down_sync(0xffffffffu, acc, o);
    if (!lane) dout[OFF_PRED + bb] = acc + bias[0];
}

// ---------------- launch ----------------
extern "C" void kernel_launch(void* const* d_in, const int* in_sizes, int n_in,
                              void* d_out, int out_size) {
    const float* x        = (const float*)d_in[0];
    const float* W1       = (const float*)d_in[1];
    const float* att_src1 = (const float*)d_in[2];
    const float* att_dst1 = (const float*)d_in[3];
    const float* b1       = (const float*)d_in[4];
    const float* W2       = (const float*)d_in[5];
    const float* att_src2 = (const float*)d_in[6];
    const float* att_dst2 = (const float*)d_in[7];
    const float* b2       = (const float*)d_in[8];
    const float* pw1      = (const float*)d_in[9];
    const float* pb1      = (const float*)d_in[10];
    const float* pw2      = (const float*)d_in[11];
    const float* pb2      = (const float*)d_in[12];
    const float* ln_w     = (const float*)d_in[13];
    const float* ln_b     = (const float*)d_in[14];
    const float* sex_emb  = (const float*)d_in[15];
    const float* mut_emb  = (const float*)d_in[16];
    const float* age_w    = (const float*)d_in[17];
    const float* age_b    = (const float*)d_in[18];
    const float* fw1      = (const float*)d_in[19];
    const float* fb1      = (const float*)d_in[20];
    const float* fw2      = (const float*)d_in[21];
    const float* fb2      = (const float*)d_in[22];
    const float* fw3      = (const float*)d_in[23];
    const float* fb3      = (const float*)d_in[24];
    const float* age      = (const float*)d_in[25];
    const int*   ei       = (const int*)d_in[26];
    const int*   sex      = (const int*)d_in[27];
    const int*   mut      = (const int*)d_in[28];

    const int Eb = in_sizes[26] / 2;
    const int Et = Eb + Nc;
    float* out = (float*)d_out;
    (void)n_in; (void)out_size;

    const int egrid = (Et + 255) / 256;
    const int warps_grid = (Nc * 32 + 255) / 256;
    const dim3 ggrid(Nc / 64, HCc / 128);

    // dynamic smem: 2*64*(K/2+1) + 2*64*17 unsigneds
    const int smem1 = (2 * 64 * (FINc / 2 + 1) + 2 * 64 * 17) * 4;  // 41984 B
    const int smem2 = (2 * 64 * (HCc / 2 + 1) + 2 * 64 * 17) * 4;   // 74752 B
    static int attr_done = 0;
    cudaFuncSetAttribute(gemm_tc_kernel<HCc>,
                         cudaFuncAttributeMaxDynamicSharedMemorySize, smem2);
    cudaFuncSetAttribute(gemm_tc_kernel<FINc>,
                         cudaFuncAttributeMaxDynamicSharedMemorySize, smem1);
    (void)attr_done;

    // launch order: gemm_tc<FINc> in slot 4 (ncu capture)
    zero_cnt_kernel<<<(Nc + 255) / 256, 256>>>();                              // 1
    csr_count_kernel<<<egrid, 256>>>(ei, Eb, Et);                              // 2
    wa_kernel<FINc><<<(FINc * Hc + 255) / 256, 256>>>(W1, att_src1, att_dst1); // 3
    gemm_tc_kernel<FINc><<<ggrid, 256, smem1>>>(x, W1, 0);                     // 4 <- profiled
    att_logits_kernel<FINc><<<Nc / 8, 256>>>(x, 0);                            // 5
    scan_kernel<<<1, 1024>>>();                                                // 6
    csr_fill_kernel<<<egrid, 256>>>(ei, Eb, Et);                               // 7
    x0_mean_kernel<<<warps_grid, 256>>>(x);                                    // 8
    gat_agg_kernel<<<Nc / 8, 256>>>(b1, pw1, pb1, Bc * NNc);                   // 9

    wa_kernel<HCc><<<(HCc * Hc + 255) / 256, 256>>>(W2, att_src2, att_dst2);
    gemm_tc_kernel<HCc><<<ggrid, 256, smem2>>>(nullptr, W2, 1);
    att_logits_kernel<HCc><<<Nc / 8, 256>>>(nullptr, 1);
    gat_agg_kernel<<<Nc / 8, 256>>>(b2, pw2, pb2, 2 * Bc * NNc);

    // ---- head ----
    ln_kernel<<<3 * Bc, 256>>>(ln_w, ln_b, out);
    demo_kernel<<<(Bc * NNc + 255) / 256, 256>>>(sex_emb, mut_emb, age_w, age_b,
                                                 age, sex, mut);
    fc1_init_kernel<<<(Bc * F1c + 255) / 256, 256>>>(fb1);
    fc1_kernel<<<Bc * FC1KT, 128>>>(fw1);
    fc2_init_kernel<<<(Bc * F2c + 255) / 256, 256>>>(fb2);
    fc2_kernel<<<Bc * FC2KT, 128>>>(fw2);
    fc3_kernel<<<1, Bc * 32>>>(fw3, fb3, out);
}

// round 13
// speedup vs baseline: 1.0332x; 1.0332x over previous
#include <cuda_runtime.h>
#include <cuda_bf16.h>

// ---------------- problem constants ----------------
#define Bc    16
#define NNc   2000
#define Nc    (Bc * NNc)        // 32000 nodes
#define FINc  128
#define Hc    4
#define Cc    64
#define HCc   256
#define EMAXT 480000
#define FCINc (6 * NNc)         // 12000
#define F1c   512
#define F2c   128
#define FC1KT 16
#define FC2KT 4

// output layout (flattened tuple: pred, x0, x1, x2, ms)
#define OFF_PRED 0
#define OFF_X0   16
#define OFF_X1   (OFF_X0 + Bc * NNc)
#define OFF_X2   (OFF_X1 + Bc * NNc)
#define OFF_MS   (OFF_X2 + Bc * NNc)

// ---------------- device scratch ----------------
__device__ float g_hin[Nc * HCc];
__device__ float g_h[Nc * HCc];
__device__ float g_as[Nc * Hc];
__device__ float g_ad[Nc * Hc];
__device__ float g_wax[HCc * 8];
__device__ int   g_cnt[Nc];
__device__ int   g_rowp[Nc + 1];
__device__ int   g_cur[Nc];
__device__ int   g_csrc[EMAXT];
__device__ float g_x[3 * Bc * NNc];
__device__ float g_t[Bc * FCINc];
__device__ float g_fc1[Bc * F1c];
__device__ float g_fc2[Bc * F2c];

// ---------------- bf16 split helpers ----------------
__device__ __forceinline__ void bsplit2(float x0, float x1,
                                        unsigned& h, unsigned& l) {
    const __nv_bfloat16 h0 = __float2bfloat16(x0);
    const __nv_bfloat16 h1 = __float2bfloat16(x1);
    const __nv_bfloat16 l0 = __float2bfloat16(x0 - __bfloat162float(h0));
    const __nv_bfloat16 l1 = __float2bfloat16(x1 - __bfloat162float(h1));
    h = (unsigned)__bfloat16_as_ushort(h0) |
        ((unsigned)__bfloat16_as_ushort(h1) << 16);
    l = (unsigned)__bfloat16_as_ushort(l0) |
        ((unsigned)__bfloat16_as_ushort(l1) << 16);
}

__device__ __forceinline__ void mma16(float* d,
                                      unsigned a0, unsigned a1,
                                      unsigned a2, unsigned a3,
                                      unsigned b0, unsigned b1) {
    asm volatile(
        "mma.sync.aligned.m16n8k16.row.col.f32.bf16.bf16.f32 "
        "{%0,%1,%2,%3}, {%4,%5,%6,%7}, {%8,%9}, {%0,%1,%2,%3};"
        : "+f"(d[0]), "+f"(d[1]), "+f"(d[2]), "+f"(d[3])
        : "r"(a0), "r"(a1), "r"(a2), "r"(a3), "r"(b0), "r"(b1));
}

// ---------------- CSR build ----------------
__global__ void zero_cnt_kernel() {
    const int i = blockIdx.x * blockDim.x + threadIdx.x;
    if (i < Nc) g_cnt[i] = 0;
}

__global__ void csr_count_kernel(const int* __restrict__ ei, int Eb, int Et) {
    const int e = blockIdx.x * blockDim.x + threadIdx.x;
    if (e >= Et) return;
    const int d = (e < Eb) ? ei[Eb + e] : (e - Eb);
    atomicAdd(&g_cnt[d], 1);
}

__global__ void scan_kernel() {
    __shared__ int partial[1024];
    const int T = 1024, CH = (Nc + T - 1) / T;
    const int t = threadIdx.x;
    const int base = t * CH;
    int s = 0;
    for (int i = 0; i < CH; ++i) {
        const int idx = base + i;
        if (idx < Nc) s += g_cnt[idx];
    }
    partial[t] = s;
    __syncthreads();
    for (int off = 1; off < T; off <<= 1) {
        int v = (t >= off) ? partial[t - off] : 0;
        __syncthreads();
        partial[t] += v;
        __syncthreads();
    }
    int run = t ? partial[t - 1] : 0;
    for (int i = 0; i < CH; ++i) {
        const int idx = base + i;
        if (idx < Nc) {
            g_rowp[idx] = run;
            g_cur[idx]  = run;
            run += g_cnt[idx];
        }
    }
    if (t == T - 1) g_rowp[Nc] = run;
}

__global__ void csr_fill_kernel(const int* __restrict__ ei, int Eb, int Et) {
    const int e = blockIdx.x * blockDim.x + threadIdx.x;
    if (e >= Et) return;
    int s, d;
    if (e < Eb) { s = ei[e]; d = ei[Eb + e]; }
    else        { s = e - Eb; d = s; }
    const int p = atomicAdd(&g_cur[d], 1);
    g_csrc[p] = s;
}

// ---------------- WA = W @ att ----------------
template <int K>
__global__ void wa_kernel(const float* __restrict__ W,
                          const float* __restrict__ attS,
                          const float* __restrict__ attD) {
    const int t = blockIdx.x * blockDim.x + threadIdx.x;
    if (t >= K * Hc) return;
    const int k = t >> 2, h = t & 3;
    float ss = 0.f, dd = 0.f;
#pragma unroll 8
    for (int c = 0; c < Cc; ++c) {
        const float w = W[k * HCc + h * Cc + c];
        ss = fmaf(w, attS[h * Cc + c], ss);
        dd = fmaf(w, attD[h * Cc + c], dd);
    }
    g_wax[k * 8 + h]     = ss;
    g_wax[k * 8 + 4 + h] = dd;
}

// ---------------- attention logits: a[n][hh] = x[n] . WA[:,hh] -------------
// use_gh selects g_h INSIDE the kernel (never pass a __device__ symbol from
// host — GB300 ATS silently dereferences the host shadow and reads zeros).
template <int K>
__global__ void __launch_bounds__(256)
att_logits_kernel(const float* __restrict__ X, int use_gh) {
    __shared__ float swa[8 * K];  // transposed: [c][k]
    const int j = threadIdx.x;
    const float* Xr = use_gh ? g_h : X;
    for (int i = j; i < K * 8; i += 256) {
        const int k = i >> 3, c = i & 7;
        swa[c * K + k] = g_wax[i];
    }
    __syncthreads();
    const int wip = j >> 5, lane = j & 31;
    const int n = blockIdx.x * 8 + wip;
    const float* xr = Xr + (size_t)n * K;
    float acc[8];
#pragma unroll
    for (int c = 0; c < 8; ++c) acc[c] = 0.f;
    for (int k = lane; k < K; k += 32) {
        const float xv = xr[k];
#pragma unroll
        for (int c = 0; c < 8; ++c)
            acc[c] = fmaf(xv, swa[c * K + k], acc[c]);
    }
#pragma unroll
    for (int o = 16; o; o >>= 1) {
#pragma unroll
        for (int c = 0; c < 8; ++c)
            acc[c] += __shfl_xor_sync(0xffffffffu, acc[c], o);
    }
    if (!lane) {
        *reinterpret_cast<float4*>(&g_as[n * Hc]) =
            make_float4(acc[0], acc[1], acc[2], acc[3]);
        *reinterpret_cast<float4*>(&g_ad[n * Hc]) =
            make_float4(acc[4], acc[5], acc[6], acc[7]);
    }
}

// ---------------- tensor-core node GEMM: hin = X @ W (bf16 3-term split) ---
// R10 configuration (best measured): static smem, grid (Nc/64, HCc/64).
template <int K>
__global__ void __launch_bounds__(256)
gemm_tc_kernel(const float* __restrict__ X, const float* __restrict__ W,
               int use_gh) {
    __shared__ unsigned xhi[64][17], xlo[64][17];
    __shared__ unsigned wh[64][17],  wl[64][17];
    const float* Xr = use_gh ? g_h : X;
    const int n0 = blockIdx.x * 64;
    const int c0 = blockIdx.y * 64;
    const int tid = threadIdx.x;
    const int warp = tid >> 5, lane = tid & 31;
    const int g = lane >> 2, t4 = lane & 3;
    const int rw = (warp & 3) * 16;
    const int cw = (warp >> 2) * 32;

    float d[4][4];
#pragma unroll
    for (int t = 0; t < 4; ++t)
#pragma unroll
        for (int i = 0; i < 4; ++i) d[t][i] = 0.f;

    for (int kc = 0; kc < K; kc += 32) {
#pragma unroll
        for (int p = 0; p < 2; ++p) {
            const int idx = tid + p * 256;
            const int r = idx >> 3, q = idx & 7;
            const float4 v = *reinterpret_cast<const float4*>(
                &Xr[(size_t)(n0 + r) * K + kc + q * 4]);
            bsplit2(v.x, v.y, xhi[r][q * 2],     xlo[r][q * 2]);
            bsplit2(v.z, v.w, xhi[r][q * 2 + 1], xlo[r][q * 2 + 1]);
        }
        {
            const int k2 = tid >> 4, n4 = tid & 15;
            const float* wp = &W[(size_t)(kc + 2 * k2) * HCc + c0 + n4 * 4];
            const float4 v0 = *reinterpret_cast<const float4*>(wp);
            const float4 v1 = *reinterpret_cast<const float4*>(wp + HCc);
            bsplit2(v0.x, v1.x, wh[n4 * 4 + 0][k2], wl[n4 * 4 + 0][k2]);
            bsplit2(v0.y, v1.y, wh[n4 * 4 + 1][k2], wl[n4 * 4 + 1][k2]);
            bsplit2(v0.z, v1.z, wh[n4 * 4 + 2][k2], wl[n4 * 4 + 2][k2]);
            bsplit2(v0.w, v1.w, wh[n4 * 4 + 3][k2], wl[n4 * 4 + 3][k2]);
        }
        __syncthreads();

#pragma unroll
        for (int ks2 = 0; ks2 < 16; ks2 += 8) {
            const unsigned a0h = xhi[rw + g][ks2 + t4];
            const unsigned a1h = xhi[rw + g + 8][ks2 + t4];
            const unsigned a2h = xhi[rw + g][ks2 + 4 + t4];
            const unsigned a3h = xhi[rw + g + 8][ks2 + 4 + t4];
            const unsigned a0l = xlo[rw + g][ks2 + t4];
            const unsigned a1l = xlo[rw + g + 8][ks2 + t4];
            const unsigned a2l = xlo[rw + g][ks2 + 4 + t4];
            const unsigned a3l = xlo[rw + g + 8][ks2 + 4 + t4];
#pragma unroll
            for (int t = 0; t < 4; ++t) {
                const int bn = cw + t * 8 + g;
                const unsigned b0h = wh[bn][ks2 + t4];
                const unsigned b1h = wh[bn][ks2 + 4 + t4];
                const unsigned b0l = wl[bn][ks2 + t4];
                const unsigned b1l = wl[bn][ks2 + 4 + t4];
                mma16(d[t], a0h, a1h, a2h, a3h, b0h, b1h);
                mma16(d[t], a0h, a1h, a2h, a3h, b0l, b1l);
                mma16(d[t], a0l, a1l, a2l, a3l, b0h, b1h);
            }
        }
        __syncthreads();
    }

    const int r  = n0 + rw + g;
    const int cc = c0 + cw + t4 * 2;
#pragma unroll
    for (int t = 0; t < 4; ++t) {
        *reinterpret_cast<float2*>(&g_hin[(size_t)r * HCc + cc + t * 8]) =
            make_float2(d[t][0], d[t][1]);
        *reinterpret_cast<float2*>(&g_hin[(size_t)(r + 8) * HCc + cc + t * 8]) =
            make_float2(d[t][2], d[t][3]);
    }
}

// ---------------- fused GAT aggregation: 2 warps per dst node -------------
// warp = one 128-col half of the node; lane = 4 cols = one LDG.128 per edge.
// Softmax without max-subtraction (logits O(1), exp fp32-safe; normalized
// ratio identical). deg<=32 fast path: stats + weights in ONE pass.
__device__ __forceinline__ float leaky02(float a) {
    return a > 0.f ? a : 0.2f * a;
}

__global__ void __launch_bounds__(256)
gat_agg_kernel(const float* __restrict__ bias,
               const float* __restrict__ pw,
               const float* __restrict__ pb,
               int xoff) {
    const int wip  = threadIdx.x >> 5;    // 0..7
    const int lane = threadIdx.x & 31;
    const int n    = blockIdx.x * 4 + (wip >> 1);
    const int half = wip & 1;
    __shared__ float s_w[8][32][4];   // UNNORMALIZED exp weights (per warp)
    __shared__ int   s_src[8][32];
    __shared__ float s_p[8];

    const int beg = g_rowp[n], end = g_rowp[n + 1];
    const int deg = end - beg;
    const float4 ad = *reinterpret_cast<const float4*>(&g_ad[n * Hc]);

    float4 sm;
    if (deg <= 32) {
        float4 w = make_float4(0.f, 0.f, 0.f, 0.f);
        if (lane < deg) {
            const int s = g_csrc[beg + lane];
            s_src[wip][lane] = s;
            const float4 as = *reinterpret_cast<const float4*>(&g_as[s * Hc]);
            w.x = __expf(leaky02(as.x + ad.x));
            w.y = __expf(leaky02(as.y + ad.y));
            w.z = __expf(leaky02(as.z + ad.z));
            w.w = __expf(leaky02(as.w + ad.w));
            *reinterpret_cast<float4*>(&s_w[wip][lane][0]) = w;
        }
        sm = w;
#pragma unroll
        for (int o = 16; o; o >>= 1) {
            sm.x += __shfl_xor_sync(0xffffffffu, sm.x, o);
            sm.y += __shfl_xor_sync(0xffffffffu, sm.y, o);
            sm.z += __shfl_xor_sync(0xffffffffu, sm.z, o);
            sm.w += __shfl_xor_sync(0xffffffffu, sm.w, o);
        }
    } else {
        sm = make_float4(0.f, 0.f, 0.f, 0.f);
        for (int e = beg + lane; e < end; e += 32) {
            const int s = g_csrc[e];
            const float4 as = *reinterpret_cast<const float4*>(&g_as[s * Hc]);
            sm.x += __expf(leaky02(as.x + ad.x));
            sm.y += __expf(leaky02(as.y + ad.y));
            sm.z += __expf(leaky02(as.z + ad.z));
            sm.w += __expf(leaky02(as.w + ad.w));
        }
#pragma unroll
        for (int o = 16; o; o >>= 1) {
            sm.x += __shfl_xor_sync(0xffffffffu, sm.x, o);
            sm.y += __shfl_xor_sync(0xffffffffu, sm.y, o);
            sm.z += __shfl_xor_sync(0xffffffffu, sm.z, o);
            sm.w += __shfl_xor_sync(0xffffffffu, sm.w, o);
        }
    }
    const float4 inv = make_float4(1.f / (sm.x + 1e-16f), 1.f / (sm.y + 1e-16f),
                                   1.f / (sm.z + 1e-16f), 1.f / (sm.w + 1e-16f));

    // gather: this warp covers cols [half*128, half*128+128); lane = 4 cols
    const int c0 = half * 128 + lane * 4;
    const int h  = c0 >> 6;
    const float invh = reinterpret_cast<const float*>(&inv)[h];
    float4 acc = make_float4(0.f, 0.f, 0.f, 0.f);

    for (int cb = beg; cb < end; cb += 32) {
        const int ne = min(32, end - cb);
        if (cb != beg || deg > 32) {
            __syncwarp();
            if (lane < ne) {
                const int s = g_csrc[cb + lane];
                s_src[wip][lane] = s;
                const float4 as = *reinterpret_cast<const float4*>(&g_as[s * Hc]);
                float4 w;
                w.x = __expf(leaky02(as.x + ad.x));
                w.y = __expf(leaky02(as.y + ad.y));
                w.z = __expf(leaky02(as.z + ad.z));
                w.w = __expf(leaky02(as.w + ad.w));
                *reinterpret_cast<float4*>(&s_w[wip][lane][0]) = w;
            }
        }
        __syncwarp();
        int e = 0;
#pragma unroll 4
        for (; e + 4 <= ne; e += 4) {
            const int   s0i = s_src[wip][e];
            const int   s1i = s_src[wip][e + 1];
            const int   s2i = s_src[wip][e + 2];
            const int   s3i = s_src[wip][e + 3];
            const float w0 = s_w[wip][e][h]     * invh;
            const float w1 = s_w[wip][e + 1][h] * invh;
            const float w2 = s_w[wip][e + 2][h] * invh;
            const float w3 = s_w[wip][e + 3][h] * invh;
            const float4 v0 = *reinterpret_cast<const float4*>(&g_hin[(size_t)s0i * HCc + c0]);
            const float4 v1 = *reinterpret_cast<const float4*>(&g_hin[(size_t)s1i * HCc + c0]);
            const float4 v2 = *reinterpret_cast<const float4*>(&g_hin[(size_t)s2i * HCc + c0]);
            const float4 v3 = *reinterpret_cast<const float4*>(&g_hin[(size_t)s3i * HCc + c0]);
            acc.x = fmaf(w0, v0.x, acc.x); acc.y = fmaf(w0, v0.y, acc.y);
            acc.z = fmaf(w0, v0.z, acc.z); acc.w = fmaf(w0, v0.w, acc.w);
            acc.x = fmaf(w1, v1.x, acc.x); acc.y = fmaf(w1, v1.y, acc.y);
            acc.z = fmaf(w1, v1.z, acc.z); acc.w = fmaf(w1, v1.w, acc.w);
            acc.x = fmaf(w2, v2.x, acc.x); acc.y = fmaf(w2, v2.y, acc.y);
            acc.z = fmaf(w2, v2.z, acc.z); acc.w = fmaf(w2, v2.w, acc.w);
            acc.x = fmaf(w3, v3.x, acc.x); acc.y = fmaf(w3, v3.y, acc.y);
            acc.z = fmaf(w3, v3.z, acc.z); acc.w = fmaf(w3, v3.w, acc.w);
        }
        for (; e < ne; ++e) {
            const int   s = s_src[wip][e];
            const float w = s_w[wip][e][h] * invh;
            const float4 v = *reinterpret_cast<const float4*>(&g_hin[(size_t)s * HCc + c0]);
            acc.x = fmaf(w, v.x, acc.x); acc.y = fmaf(w, v.y, acc.y);
            acc.z = fmaf(w, v.z, acc.z); acc.w = fmaf(w, v.w, acc.w);
        }
    }

    // epilogue: bias + relu + store + pooled projection (pair reduction)
    const float4 bv = *reinterpret_cast<const float4*>(&bias[c0]);
    float4 r;
    r.x = fmaxf(acc.x + bv.x, 0.f); r.y = fmaxf(acc.y + bv.y, 0.f);
    r.z = fmaxf(acc.z + bv.z, 0.f); r.w = fmaxf(acc.w + bv.w, 0.f);
    *reinterpret_cast<float4*>(&g_h[(size_t)n * HCc + c0]) = r;

    const float4 pv = *reinterpret_cast<const float4*>(&pw[c0]);
    float p = r.x * pv.x + r.y * pv.y + r.z * pv.z + r.w * pv.w;
#pragma unroll
    for (int o = 16; o; o >>= 1) p += __shfl_xor_sync(0xffffffffu, p, o);
    if (!lane) s_p[wip] = p;
    __syncthreads();
    if (!half && !lane) g_x[xoff + n] = s_p[wip] + s_p[wip + 1] + pb[0];
}

// ---------------- misc ----------------
__global__ void x0_mean_kernel(const float* __restrict__ x) {
    const int warp = (blockIdx.x * blockDim.x + threadIdx.x) >> 5;
    const int lane = threadIdx.x & 31;
    if (warp >= Nc) return;
    const float4 v = reinterpret_cast<const float4*>(x + (size_t)warp * FINc)[lane];
    float s = v.x + v.y + v.z + v.w;
    for (int o = 16; o; o >>= 1) s += __shfl_down_sync(0xffffffffu, s, o);
    if (!lane) g_x[warp] = s * (1.0f / FINc);
}

__global__ void ln_kernel(const float* __restrict__ w,
                          const float* __restrict__ b,
                          float* __restrict__ dout) {
    const int a  = blockIdx.x / Bc;
    const int bb = blockIdx.x % Bc;
    const float* src = g_x + a * Bc * NNc + bb * NNc;
    __shared__ float rs[256], rq[256];
    float s = 0.f, q = 0.f;
    for (int i = threadIdx.x; i < NNc; i += 256) {
        const float v = src[i];
        s += v; q += v * v;
    }
    rs[threadIdx.x] = s; rq[threadIdx.x] = q;
    __syncthreads();
    for (int o = 128; o; o >>= 1) {
        if (threadIdx.x < o) {
            rs[threadIdx.x] += rs[threadIdx.x + o];
            rq[threadIdx.x] += rq[threadIdx.x + o];
        }
        __syncthreads();
    }
    const float mu  = rs[0] * (1.0f / NNc);
    const float var = rq[0] * (1.0f / NNc) - mu * mu;
    const float inv = rsqrtf(var + 1e-5f);
    for (int i = threadIdx.x; i < NNc; i += 256) {
        const float y = (src[i] - mu) * inv * w[i] + b[i];
        dout[OFF_X0 + a * Bc * NNc + bb * NNc + i] = y;
        dout[OFF_MS + bb * 3 * NNc + a * NNc + i] = y;
        g_t[bb * FCINc + 3 * NNc + a * NNc + i]   = y;
    }
}

__global__ void demo_kernel(const float* __restrict__ sex_emb,
                            const float* __restrict__ mut_emb,
                            const float* __restrict__ age_w,
                            const float* __restrict__ age_b,
                            const float* __restrict__ age,
                            const int* __restrict__ sex,
                            const int* __restrict__ mut) {
    const int i = blockIdx.x * blockDim.x + threadIdx.x;
    if (i >= Bc * NNc) return;
    const int bb = i / NNc, i2 = i % NNc;
    g_t[bb * FCINc + i2]            = sex_emb[sex[bb] * NNc + i2];
    g_t[bb * FCINc + NNc + i2]      = mut_emb[mut[bb] * NNc + i2];
    g_t[bb * FCINc + 2 * NNc + i2]  = fmaf(age[bb], age_w[i2], age_b[i2]);
}

__global__ void fc1_init_kernel(const float* __restrict__ bias) {
    const int i = blockIdx.x * blockDim.x + threadIdx.x;
    if (i < Bc * F1c) g_fc1[i] = bias[i & (F1c - 1)];
}

__global__ void fc1_kernel(const float* __restrict__ w) {
    __shared__ float ts[FCINc / FC1KT];
    const int bb = blockIdx.x >> 4;
    const int kt = blockIdx.x & (FC1KT - 1);
    const int k0 = kt * (FCINc / FC1KT);
    for (int k = threadIdx.x; k < FCINc / FC1KT; k += 128)
        ts[k] = g_t[bb * FCINc + k0 + k];
    __syncthreads();
    const int j4 = threadIdx.x * 4;
    float4 a0 = make_float4(0, 0, 0, 0), a1 = make_float4(0, 0, 0, 0);
    for (int k = 0; k < FCINc / FC1KT; k += 2) {
        const float t0 = ts[k], t1 = ts[k + 1];
        const float4 w0 = *reinterpret_cast<const float4*>(&w[(size_t)(k0 + k) * F1c + j4]);
        const float4 w1 = *reinterpret_cast<const float4*>(&w[(size_t)(k0 + k + 1) * F1c + j4]);
        a0.x = fmaf(t0, w0.x, a0.x); a1.x = fmaf(t1, w1.x, a1.x);
        a0.y = fmaf(t0, w0.y, a0.y); a1.y = fmaf(t1, w1.y, a1.y);
        a0.z = fmaf(t0, w0.z, a0.z); a1.z = fmaf(t1, w1.z, a1.z);
        a0.w = fmaf(t0, w0.w, a0.w); a1.w = fmaf(t1, w1.w, a1.w);
    }
    atomicAdd(&g_fc1[bb * F1c + j4 + 0], a0.x + a1.x);
    atomicAdd(&g_fc1[bb * F1c + j4 + 1], a0.y + a1.y);
    atomicAdd(&g_fc1[bb * F1c + j4 + 2], a0.z + a1.z);
    atomicAdd(&g_fc1[bb * F1c + j4 + 3], a0.w + a1.w);
}

__global__ void fc2_init_kernel(const float* __restrict__ bias) {
    const int i = blockIdx.x * blockDim.x + threadIdx.x;
    if (i < Bc * F2c) g_fc2[i] = bias[i & (F2c - 1)];
}

__global__ void fc2_kernel(const float* __restrict__ w) {
    __shared__ float ts[F1c / FC2KT];
    const int bb = blockIdx.x >> 2;
    const int kt = blockIdx.x & (FC2KT - 1);
    const int k0 = kt * (F1c / FC2KT);
    for (int k = threadIdx.x; k < F1c / FC2KT; k += 128)
        ts[k] = fmaxf(g_fc1[bb * F1c + k0 + k], 0.f);
    __syncthreads();
    const int j = threadIdx.x;
    float a0 = 0.f, a1 = 0.f;
    for (int k = 0; k < F1c / FC2KT; k += 2) {
        a0 = fmaf(ts[k],     w[(size_t)(k0 + k) * F2c + j],     a0);
        a1 = fmaf(ts[k + 1], w[(size_t)(k0 + k + 1) * F2c + j], a1);
    }
    atomicAdd(&g_fc2[bb * F2c + j], a0 + a1);
}

__global__ void fc3_kernel(const float* __restrict__ w,
                           const float* __restrict__ bias,
                           float* __restrict__ dout) {
    const int bb = threadIdx.x >> 5;
    const int lane = threadIdx.x & 31;
    float acc = 0.f;
    for (int k = lane; k < F2c; k += 32)
        acc += fmaxf(g_fc2[bb * F2c + k], 0.f) * w[k];
    for (int o = 16; o; o >>= 1) acc += __shfl_down_sync(0xffffffffu, acc, o);
    if (!lane) dout[OFF_PRED + bb] = acc + bias[0];
}

// ---------------- launch ----------------
extern "C" void kernel_launch(void* const* d_in, const int* in_sizes, int n_in,
                              void* d_out, int out_size) {
    const float* x        = (const float*)d_in[0];
    const float* W1       = (const float*)d_in[1];
    const float* att_src1 = (const float*)d_in[2];
    const float* att_dst1 = (const float*)d_in[3];
    const float* b1       = (const float*)d_in[4];
    const float* W2       = (const float*)d_in[5];
    const float* att_src2 = (const float*)d_in[6];
    const float* att_dst2 = (const float*)d_in[7];
    const float* b2       = (const float*)d_in[8];
    const float* pw1      = (const float*)d_in[9];
    const float* pb1      = (const float*)d_in[10];
    const float* pw2      = (const float*)d_in[11];
    const float* pb2      = (const float*)d_in[12];
    const float* ln_w     = (const float*)d_in[13];
    const float* ln_b     = (const float*)d_in[14];
    const float* sex_emb  = (const float*)d_in[15];
    const float* mut_emb  = (const float*)d_in[16];
    const float* age_w    = (const float*)d_in[17];
    const float* age_b    = (const float*)d_in[18];
    const float* fw1      = (const float*)d_in[19];
    const float* fb1      = (const float*)d_in[20];
    const float* fw2      = (const float*)d_in[21];
    const float* fb2      = (const float*)d_in[22];
    const float* fw3      = (const float*)d_in[23];
    const float* fb3      = (const float*)d_in[24];
    const float* age      = (const float*)d_in[25];
    const int*   ei       = (const int*)d_in[26];
    const int*   sex      = (const int*)d_in[27];
    const int*   mut      = (const int*)d_in[28];

    const int Eb = in_sizes[26] / 2;
    const int Et = Eb + Nc;
    float* out = (float*)d_out;
    (void)n_in; (void)out_size;

    const int egrid = (Et + 255) / 256;
    const int warps_grid = (Nc * 32 + 255) / 256;
    const dim3 ggrid(Nc / 64, HCc / 64);

    // launch order: gemm_tc<FINc> in slot 4 (ncu capture)
    zero_cnt_kernel<<<(Nc + 255) / 256, 256>>>();                              // 1
    csr_count_kernel<<<egrid, 256>>>(ei, Eb, Et);                              // 2
    wa_kernel<FINc><<<(FINc * Hc + 255) / 256, 256>>>(W1, att_src1, att_dst1); // 3
    gemm_tc_kernel<FINc><<<ggrid, 256>>>(x, W1, 0);                            // 4 <- profiled
    att_logits_kernel<FINc><<<Nc / 8, 256>>>(x, 0);                            // 5
    scan_kernel<<<1, 1024>>>();                                                // 6
    csr_fill_kernel<<<egrid, 256>>>(ei, Eb, Et);                               // 7
    x0_mean_kernel<<<warps_grid, 256>>>(x);                                    // 8
    gat_agg_kernel<<<Nc / 4, 256>>>(b1, pw1, pb1, Bc * NNc);                   // 9

    wa_kernel<HCc><<<(HCc * Hc + 255) / 256, 256>>>(W2, att_src2, att_dst2);
    gemm_tc_kernel<HCc><<<ggrid, 256>>>(nullptr, W2, 1);
    att_logits_kernel<HCc><<<Nc / 8, 256>>>(nullptr, 1);
    gat_agg_kernel<<<Nc / 4, 256>>>(b2, pw2, pb2, 2 * Bc * NNc);

    // ---- head ----
    ln_kernel<<<3 * Bc, 256>>>(ln_w, ln_b, out);
    demo_kernel<<<(Bc * NNc + 255) / 256, 256>>>(sex_emb, mut_emb, age_w, age_b,
                                                 age, sex, mut);
    fc1_init_kernel<<<(Bc * F1c + 255) / 256, 256>>>(fb1);
    fc1_kernel<<<Bc * FC1KT, 128>>>(fw1);
    fc2_init_kernel<<<(Bc * F2c + 255) / 256, 256>>>(fb2);
    fc2_kernel<<<Bc * FC2KT, 128>>>(fw2);
    fc3_kernel<<<1, Bc * 32>>>(fw3, fb3, out);
}

// round 14
// speedup vs baseline: 1.0453x; 1.0117x over previous
#include <cuda_runtime.h>
#include <cuda_bf16.h>

// ---------------- problem constants ----------------
#define Bc    16
#define NNc   2000
#define Nc    (Bc * NNc)        // 32000 nodes
#define FINc  128
#define Hc    4
#define Cc    64
#define HCc   256
#define EMAXT 480000
#define FCINc (6 * NNc)         // 12000
#define F1c   512
#define F2c   128
#define FC1KT 16
#define FC2KT 4
#define SP    20                // gemm smem row stride (conflict-free)

// output layout (flattened tuple: pred, x0, x1, x2, ms)
#define OFF_PRED 0
#define OFF_X0   16
#define OFF_X1   (OFF_X0 + Bc * NNc)
#define OFF_X2   (OFF_X1 + Bc * NNc)
#define OFF_MS   (OFF_X2 + Bc * NNc)

// ---------------- device scratch ----------------
__device__ float g_hin[Nc * HCc];
__device__ float g_h[Nc * HCc];
__device__ float g_as[Nc * Hc];
__device__ float g_ad[Nc * Hc];
__device__ float g_wax[HCc * 8];    // layer 1 (only FINc*8 used)
__device__ float g_wax2[HCc * 8];   // layer 2
__device__ int   g_cnt[Nc];
__device__ int   g_rowp[Nc + 1];
__device__ int   g_cur[Nc];
__device__ int   g_csrc[EMAXT];
__device__ float g_x[3 * Bc * NNc];
__device__ float g_t[Bc * FCINc];
__device__ float g_fc1[Bc * F1c];
__device__ float g_fc2[Bc * F2c];

// ---------------- bf16 split helpers ----------------
__device__ __forceinline__ void bsplit2(float x0, float x1,
                                        unsigned& h, unsigned& l) {
    const __nv_bfloat16 h0 = __float2bfloat16(x0);
    const __nv_bfloat16 h1 = __float2bfloat16(x1);
    const __nv_bfloat16 l0 = __float2bfloat16(x0 - __bfloat162float(h0));
    const __nv_bfloat16 l1 = __float2bfloat16(x1 - __bfloat162float(h1));
    h = (unsigned)__bfloat16_as_ushort(h0) |
        ((unsigned)__bfloat16_as_ushort(h1) << 16);
    l = (unsigned)__bfloat16_as_ushort(l0) |
        ((unsigned)__bfloat16_as_ushort(l1) << 16);
}

__device__ __forceinline__ void mma16(float* d,
                                      unsigned a0, unsigned a1,
                                      unsigned a2, unsigned a3,
                                      unsigned b0, unsigned b1) {
    asm volatile(
        "mma.sync.aligned.m16n8k16.row.col.f32.bf16.bf16.f32 "
        "{%0,%1,%2,%3}, {%4,%5,%6,%7}, {%8,%9}, {%0,%1,%2,%3};"
        : "+f"(d[0]), "+f"(d[1]), "+f"(d[2]), "+f"(d[3])
        : "r"(a0), "r"(a1), "r"(a2), "r"(a3), "r"(b0), "r"(b1));
}

// ---------------- fused setup: x0_mean + zero_cnt + demo + fc init --------
__global__ void __launch_bounds__(256)
setup_kernel(const float* __restrict__ x,
             const float* __restrict__ sex_emb,
             const float* __restrict__ mut_emb,
             const float* __restrict__ age_w,
             const float* __restrict__ age_b,
             const float* __restrict__ age,
             const int* __restrict__ sex,
             const int* __restrict__ mut,
             const float* __restrict__ fb1,
             const float* __restrict__ fb2) {
    const int b = blockIdx.x;
    if (b < 4000) {                       // x0_mean: warp per node
        const int warp = b * 8 + (threadIdx.x >> 5);
        const int lane = threadIdx.x & 31;
        const float4 v =
            reinterpret_cast<const float4*>(x + (size_t)warp * FINc)[lane];
        float s = v.x + v.y + v.z + v.w;
        for (int o = 16; o; o >>= 1) s += __shfl_down_sync(0xffffffffu, s, o);
        if (!lane) g_x[warp] = s * (1.0f / FINc);
    } else if (b < 4125) {                // zero_cnt
        const int i = (b - 4000) * 256 + threadIdx.x;
        if (i < Nc) g_cnt[i] = 0;
    } else if (b < 4250) {                // demo
        const int i = (b - 4125) * 256 + threadIdx.x;
        if (i < Bc * NNc) {
            const int bb = i / NNc, i2 = i % NNc;
            g_t[bb * FCINc + i2]           = sex_emb[sex[bb] * NNc + i2];
            g_t[bb * FCINc + NNc + i2]     = mut_emb[mut[bb] * NNc + i2];
            g_t[bb * FCINc + 2 * NNc + i2] = fmaf(age[bb], age_w[i2], age_b[i2]);
        }
    } else if (b < 4282) {                // fc1_init
        const int i = (b - 4250) * 256 + threadIdx.x;
        if (i < Bc * F1c) g_fc1[i] = fb1[i & (F1c - 1)];
    } else {                              // fc2_init
        const int i = (b - 4282) * 256 + threadIdx.x;
        if (i < Bc * F2c) g_fc2[i] = fb2[i & (F2c - 1)];
    }
}

// ---------------- CSR build ----------------
__global__ void csr_count_kernel(const int* __restrict__ ei, int Eb, int Et) {
    const int e = blockIdx.x * blockDim.x + threadIdx.x;
    if (e >= Et) return;
    const int d = (e < Eb) ? ei[Eb + e] : (e - Eb);
    atomicAdd(&g_cnt[d], 1);
}

__global__ void scan_kernel() {
    __shared__ int partial[1024];
    const int T = 1024, CH = (Nc + T - 1) / T;
    const int t = threadIdx.x;
    const int base = t * CH;
    int s = 0;
    for (int i = 0; i < CH; ++i) {
        const int idx = base + i;
        if (idx < Nc) s += g_cnt[idx];
    }
    partial[t] = s;
    __syncthreads();
    for (int off = 1; off < T; off <<= 1) {
        int v = (t >= off) ? partial[t - off] : 0;
        __syncthreads();
        partial[t] += v;
        __syncthreads();
    }
    int run = t ? partial[t - 1] : 0;
    for (int i = 0; i < CH; ++i) {
        const int idx = base + i;
        if (idx < Nc) {
            g_rowp[idx] = run;
            g_cur[idx]  = run;
            run += g_cnt[idx];
        }
    }
    if (t == T - 1) g_rowp[Nc] = run;
}

__global__ void csr_fill_kernel(const int* __restrict__ ei, int Eb, int Et) {
    const int e = blockIdx.x * blockDim.x + threadIdx.x;
    if (e >= Et) return;
    int s, d;
    if (e < Eb) { s = ei[e]; d = ei[Eb + e]; }
    else        { s = e - Eb; d = s; }
    const int p = atomicAdd(&g_cur[d], 1);
    g_csrc[p] = s;
}

// ---------------- WA = W @ att (both layers in one kernel) ----------------
__global__ void wa_all_kernel(const float* __restrict__ W1,
                              const float* __restrict__ attS1,
                              const float* __restrict__ attD1,
                              const float* __restrict__ W2,
                              const float* __restrict__ attS2,
                              const float* __restrict__ attD2) {
    const int t = blockIdx.x * blockDim.x + threadIdx.x;
    const int L1T = FINc * Hc;  // 512
    if (t < L1T) {
        const int k = t >> 2, h = t & 3;
        float ss = 0.f, dd = 0.f;
#pragma unroll 8
        for (int c = 0; c < Cc; ++c) {
            const float w = W1[k * HCc + h * Cc + c];
            ss = fmaf(w, attS1[h * Cc + c], ss);
            dd = fmaf(w, attD1[h * Cc + c], dd);
        }
        g_wax[k * 8 + h]     = ss;
        g_wax[k * 8 + 4 + h] = dd;
    } else if (t < L1T + HCc * Hc) {
        const int t2 = t - L1T;
        const int k = t2 >> 2, h = t2 & 3;
        float ss = 0.f, dd = 0.f;
#pragma unroll 8
        for (int c = 0; c < Cc; ++c) {
            const float w = W2[k * HCc + h * Cc + c];
            ss = fmaf(w, attS2[h * Cc + c], ss);
            dd = fmaf(w, attD2[h * Cc + c], dd);
        }
        g_wax2[k * 8 + h]     = ss;
        g_wax2[k * 8 + 4 + h] = dd;
    }
}

// ---------------- attention logits: a[n][hh] = x[n] . WA[:,hh] -------------
// use_gh selects g_h AND g_wax2 INSIDE the kernel (never pass a __device__
// symbol from host — GB300 ATS silently reads the host shadow as zeros).
template <int K>
__global__ void __launch_bounds__(256)
att_logits_kernel(const float* __restrict__ X, int use_gh) {
    __shared__ float swa[8 * K];  // transposed: [c][k]
    const int j = threadIdx.x;
    const float* Xr = use_gh ? g_h : X;
    const float* wax = use_gh ? g_wax2 : g_wax;
    for (int i = j; i < K * 8; i += 256) {
        const int k = i >> 3, c = i & 7;
        swa[c * K + k] = wax[i];
    }
    __syncthreads();
    const int wip = j >> 5, lane = j & 31;
    const int n = blockIdx.x * 8 + wip;
    const float* xr = Xr + (size_t)n * K;
    float acc[8];
#pragma unroll
    for (int c = 0; c < 8; ++c) acc[c] = 0.f;
    for (int k = lane; k < K; k += 32) {
        const float xv = xr[k];
#pragma unroll
        for (int c = 0; c < 8; ++c)
            acc[c] = fmaf(xv, swa[c * K + k], acc[c]);
    }
#pragma unroll
    for (int o = 16; o; o >>= 1) {
#pragma unroll
        for (int c = 0; c < 8; ++c)
            acc[c] += __shfl_xor_sync(0xffffffffu, acc[c], o);
    }
    if (!lane) {
        *reinterpret_cast<float4*>(&g_as[n * Hc]) =
            make_float4(acc[0], acc[1], acc[2], acc[3]);
        *reinterpret_cast<float4*>(&g_ad[n * Hc]) =
            make_float4(acc[4], acc[5], acc[6], acc[7]);
    }
}

// ---------------- tensor-core node GEMM: hin = X @ W (bf16 3-term split) ---
// R10 config; smem row stride SP=20 -> MMA-loop LDS are bank-conflict-free.
template <int K>
__global__ void __launch_bounds__(256)
gemm_tc_kernel(const float* __restrict__ X, const float* __restrict__ W,
               int use_gh) {
    __shared__ unsigned xhi[64][SP], xlo[64][SP];
    __shared__ unsigned wh[64][SP],  wl[64][SP];
    const float* Xr = use_gh ? g_h : X;
    const int n0 = blockIdx.x * 64;
    const int c0 = blockIdx.y * 64;
    const int tid = threadIdx.x;
    const int warp = tid >> 5, lane = tid & 31;
    const int g = lane >> 2, t4 = lane & 3;
    const int rw = (warp & 3) * 16;
    const int cw = (warp >> 2) * 32;

    float d[4][4];
#pragma unroll
    for (int t = 0; t < 4; ++t)
#pragma unroll
        for (int i = 0; i < 4; ++i) d[t][i] = 0.f;

    for (int kc = 0; kc < K; kc += 32) {
#pragma unroll
        for (int p = 0; p < 2; ++p) {
            const int idx = tid + p * 256;
            const int r = idx >> 3, q = idx & 7;
            const float4 v = *reinterpret_cast<const float4*>(
                &Xr[(size_t)(n0 + r) * K + kc + q * 4]);
            bsplit2(v.x, v.y, xhi[r][q * 2],     xlo[r][q * 2]);
            bsplit2(v.z, v.w, xhi[r][q * 2 + 1], xlo[r][q * 2 + 1]);
        }
        {
            const int k2 = tid >> 4, n4 = tid & 15;
            const float* wp = &W[(size_t)(kc + 2 * k2) * HCc + c0 + n4 * 4];
            const float4 v0 = *reinterpret_cast<const float4*>(wp);
            const float4 v1 = *reinterpret_cast<const float4*>(wp + HCc);
            bsplit2(v0.x, v1.x, wh[n4 * 4 + 0][k2], wl[n4 * 4 + 0][k2]);
            bsplit2(v0.y, v1.y, wh[n4 * 4 + 1][k2], wl[n4 * 4 + 1][k2]);
            bsplit2(v0.z, v1.z, wh[n4 * 4 + 2][k2], wl[n4 * 4 + 2][k2]);
            bsplit2(v0.w, v1.w, wh[n4 * 4 + 3][k2], wl[n4 * 4 + 3][k2]);
        }
        __syncthreads();

#pragma unroll
        for (int ks2 = 0; ks2 < 16; ks2 += 8) {
            const unsigned a0h = xhi[rw + g][ks2 + t4];
            const unsigned a1h = xhi[rw + g + 8][ks2 + t4];
            const unsigned a2h = xhi[rw + g][ks2 + 4 + t4];
            const unsigned a3h = xhi[rw + g + 8][ks2 + 4 + t4];
            const unsigned a0l = xlo[rw + g][ks2 + t4];
            const unsigned a1l = xlo[rw + g + 8][ks2 + t4];
            const unsigned a2l = xlo[rw + g][ks2 + 4 + t4];
            const unsigned a3l = xlo[rw + g + 8][ks2 + 4 + t4];
#pragma unroll
            for (int t = 0; t < 4; ++t) {
                const int bn = cw + t * 8 + g;
                const unsigned b0h = wh[bn][ks2 + t4];
                const unsigned b1h = wh[bn][ks2 + 4 + t4];
                const unsigned b0l = wl[bn][ks2 + t4];
                const unsigned b1l = wl[bn][ks2 + 4 + t4];
                mma16(d[t], a0h, a1h, a2h, a3h, b0h, b1h);
                mma16(d[t], a0h, a1h, a2h, a3h, b0l, b1l);
                mma16(d[t], a0l, a1l, a2l, a3l, b0h, b1h);
            }
        }
        __syncthreads();
    }

    const int r  = n0 + rw + g;
    const int cc = c0 + cw + t4 * 2;
#pragma unroll
    for (int t = 0; t < 4; ++t) {
        *reinterpret_cast<float2*>(&g_hin[(size_t)r * HCc + cc + t * 8]) =
            make_float2(d[t][0], d[t][1]);
        *reinterpret_cast<float2*>(&g_hin[(size_t)(r + 8) * HCc + cc + t * 8]) =
            make_float2(d[t][2], d[t][3]);
    }
}

// ---------------- fused GAT aggregation: 2 warps per dst node -------------
__device__ __forceinline__ float leaky02(float a) {
    return a > 0.f ? a : 0.2f * a;
}

__global__ void __launch_bounds__(256)
gat_agg_kernel(const float* __restrict__ bias,
               const float* __restrict__ pw,
               const float* __restrict__ pb,
               int xoff) {
    const int wip  = threadIdx.x >> 5;    // 0..7
    const int lane = threadIdx.x & 31;
    const int n    = blockIdx.x * 4 + (wip >> 1);
    const int half = wip & 1;
    __shared__ float s_w[8][32][4];   // UNNORMALIZED exp weights (per warp)
    __shared__ int   s_src[8][32];
    __shared__ float s_p[8];

    const int beg = g_rowp[n], end = g_rowp[n + 1];
    const int deg = end - beg;
    const float4 ad = *reinterpret_cast<const float4*>(&g_ad[n * Hc]);

    float4 sm;
    if (deg <= 32) {
        float4 w = make_float4(0.f, 0.f, 0.f, 0.f);
        if (lane < deg) {
            const int s = g_csrc[beg + lane];
            s_src[wip][lane] = s;
            const float4 as = *reinterpret_cast<const float4*>(&g_as[s * Hc]);
            w.x = __expf(leaky02(as.x + ad.x));
            w.y = __expf(leaky02(as.y + ad.y));
            w.z = __expf(leaky02(as.z + ad.z));
            w.w = __expf(leaky02(as.w + ad.w));
            *reinterpret_cast<float4*>(&s_w[wip][lane][0]) = w;
        }
        sm = w;
#pragma unroll
        for (int o = 16; o; o >>= 1) {
            sm.x += __shfl_xor_sync(0xffffffffu, sm.x, o);
            sm.y += __shfl_xor_sync(0xffffffffu, sm.y, o);
            sm.z += __shfl_xor_sync(0xffffffffu, sm.z, o);
            sm.w += __shfl_xor_sync(0xffffffffu, sm.w, o);
        }
    } else {
        sm = make_float4(0.f, 0.f, 0.f, 0.f);
        for (int e = beg + lane; e < end; e += 32) {
            const int s = g_csrc[e];
            const float4 as = *reinterpret_cast<const float4*>(&g_as[s * Hc]);
            sm.x += __expf(leaky02(as.x + ad.x));
            sm.y += __expf(leaky02(as.y + ad.y));
            sm.z += __expf(leaky02(as.z + ad.z));
            sm.w += __expf(leaky02(as.w + ad.w));
        }
#pragma unroll
        for (int o = 16; o; o >>= 1) {
            sm.x += __shfl_xor_sync(0xffffffffu, sm.x, o);
            sm.y += __shfl_xor_sync(0xffffffffu, sm.y, o);
            sm.z += __shfl_xor_sync(0xffffffffu, sm.z, o);
            sm.w += __shfl_xor_sync(0xffffffffu, sm.w, o);
        }
    }
    const float4 inv = make_float4(1.f / (sm.x + 1e-16f), 1.f / (sm.y + 1e-16f),
                                   1.f / (sm.z + 1e-16f), 1.f / (sm.w + 1e-16f));

    const int c0 = half * 128 + lane * 4;
    const int h  = c0 >> 6;
    const float invh = reinterpret_cast<const float*>(&inv)[h];
    float4 acc = make_float4(0.f, 0.f, 0.f, 0.f);

    for (int cb = beg; cb < end; cb += 32) {
        const int ne = min(32, end - cb);
        if (cb != beg || deg > 32) {
            __syncwarp();
            if (lane < ne) {
                const int s = g_csrc[cb + lane];
                s_src[wip][lane] = s;
                const float4 as = *reinterpret_cast<const float4*>(&g_as[s * Hc]);
                float4 w;
                w.x = __expf(leaky02(as.x + ad.x));
                w.y = __expf(leaky02(as.y + ad.y));
                w.z = __expf(leaky02(as.z + ad.z));
                w.w = __expf(leaky02(as.w + ad.w));
                *reinterpret_cast<float4*>(&s_w[wip][lane][0]) = w;
            }
        }
        __syncwarp();
        int e = 0;
#pragma unroll 4
        for (; e + 4 <= ne; e += 4) {
            const int   s0i = s_src[wip][e];
            const int   s1i = s_src[wip][e + 1];
            const int   s2i = s_src[wip][e + 2];
            const int   s3i = s_src[wip][e + 3];
            const float w0 = s_w[wip][e][h]     * invh;
            const float w1 = s_w[wip][e + 1][h] * invh;
            const float w2 = s_w[wip][e + 2][h] * invh;
            const float w3 = s_w[wip][e + 3][h] * invh;
            const float4 v0 = *reinterpret_cast<const float4*>(&g_hin[(size_t)s0i * HCc + c0]);
            const float4 v1 = *reinterpret_cast<const float4*>(&g_hin[(size_t)s1i * HCc + c0]);
            const float4 v2 = *reinterpret_cast<const float4*>(&g_hin[(size_t)s2i * HCc + c0]);
            const float4 v3 = *reinterpret_cast<const float4*>(&g_hin[(size_t)s3i * HCc + c0]);
            acc.x = fmaf(w0, v0.x, acc.x); acc.y = fmaf(w0, v0.y, acc.y);
            acc.z = fmaf(w0, v0.z, acc.z); acc.w = fmaf(w0, v0.w, acc.w);
            acc.x = fmaf(w1, v1.x, acc.x); acc.y = fmaf(w1, v1.y, acc.y);
            acc.z = fmaf(w1, v1.z, acc.z); acc.w = fmaf(w1, v1.w, acc.w);
            acc.x = fmaf(w2, v2.x, acc.x); acc.y = fmaf(w2, v2.y, acc.y);
            acc.z = fmaf(w2, v2.z, acc.z); acc.w = fmaf(w2, v2.w, acc.w);
            acc.x = fmaf(w3, v3.x, acc.x); acc.y = fmaf(w3, v3.y, acc.y);
            acc.z = fmaf(w3, v3.z, acc.z); acc.w = fmaf(w3, v3.w, acc.w);
        }
        for (; e < ne; ++e) {
            const int   s = s_src[wip][e];
            const float w = s_w[wip][e][h] * invh;
            const float4 v = *reinterpret_cast<const float4*>(&g_hin[(size_t)s * HCc + c0]);
            acc.x = fmaf(w, v.x, acc.x); acc.y = fmaf(w, v.y, acc.y);
            acc.z = fmaf(w, v.z, acc.z); acc.w = fmaf(w, v.w, acc.w);
        }
    }

    const float4 bv = *reinterpret_cast<const float4*>(&bias[c0]);
    float4 r;
    r.x = fmaxf(acc.x + bv.x, 0.f); r.y = fmaxf(acc.y + bv.y, 0.f);
    r.z = fmaxf(acc.z + bv.z, 0.f); r.w = fmaxf(acc.w + bv.w, 0.f);
    *reinterpret_cast<float4*>(&g_h[(size_t)n * HCc + c0]) = r;

    const float4 pv = *reinterpret_cast<const float4*>(&pw[c0]);
    float p = r.x * pv.x + r.y * pv.y + r.z * pv.z + r.w * pv.w;
#pragma unroll
    for (int o = 16; o; o >>= 1) p += __shfl_xor_sync(0xffffffffu, p, o);
    if (!lane) s_p[wip] = p;
    __syncthreads();
    if (!half && !lane) g_x[xoff + n] = s_p[wip] + s_p[wip + 1] + pb[0];
}

// ---------------- head ----------------
__global__ void ln_kernel(const float* __restrict__ w,
                          const float* __restrict__ b,
                          float* __restrict__ dout) {
    const int a  = blockIdx.x / Bc;
    const int bb = blockIdx.x % Bc;
    const float* src = g_x + a * Bc * NNc + bb * NNc;
    __shared__ float rs[256], rq[256];
    float s = 0.f, q = 0.f;
    for (int i = threadIdx.x; i < NNc; i += 256) {
        const float v = src[i];
        s += v; q += v * v;
    }
    rs[threadIdx.x] = s; rq[threadIdx.x] = q;
    __syncthreads();
    for (int o = 128; o; o >>= 1) {
        if (threadIdx.x < o) {
            rs[threadIdx.x] += rs[threadIdx.x + o];
            rq[threadIdx.x] += rq[threadIdx.x + o];
        }
        __syncthreads();
    }
    const float mu  = rs[0] * (1.0f / NNc);
    const float var = rq[0] * (1.0f / NNc) - mu * mu;
    const float inv = rsqrtf(var + 1e-5f);
    for (int i = threadIdx.x; i < NNc; i += 256) {
        const float y = (src[i] - mu) * inv * w[i] + b[i];
        dout[OFF_X0 + a * Bc * NNc + bb * NNc + i] = y;
        dout[OFF_MS + bb * 3 * NNc + a * NNc + i] = y;
        g_t[bb * FCINc + 3 * NNc + a * NNc + i]   = y;
    }
}

__global__ void fc1_kernel(const float* __restrict__ w) {
    __shared__ float ts[FCINc / FC1KT];
    const int bb = blockIdx.x >> 4;
    const int kt = blockIdx.x & (FC1KT - 1);
    const int k0 = kt * (FCINc / FC1KT);
    for (int k = threadIdx.x; k < FCINc / FC1KT; k += 128)
        ts[k] = g_t[bb * FCINc + k0 + k];
    __syncthreads();
    const int j4 = threadIdx.x * 4;
    float4 a0 = make_float4(0, 0, 0, 0), a1 = make_float4(0, 0, 0, 0);
    for (int k = 0; k < FCINc / FC1KT; k += 2) {
        const float t0 = ts[k], t1 = ts[k + 1];
        const float4 w0 = *reinterpret_cast<const float4*>(&w[(size_t)(k0 + k) * F1c + j4]);
        const float4 w1 = *reinterpret_cast<const float4*>(&w[(size_t)(k0 + k + 1) * F1c + j4]);
        a0.x = fmaf(t0, w0.x, a0.x); a1.x = fmaf(t1, w1.x, a1.x);
        a0.y = fmaf(t0, w0.y, a0.y); a1.y = fmaf(t1, w1.y, a1.y);
        a0.z = fmaf(t0, w0.z, a0.z); a1.z = fmaf(t1, w1.z, a1.z);
        a0.w = fmaf(t0, w0.w, a0.w); a1.w = fmaf(t1, w1.w, a1.w);
    }
    atomicAdd(&g_fc1[bb * F1c + j4 + 0], a0.x + a1.x);
    atomicAdd(&g_fc1[bb * F1c + j4 + 1], a0.y + a1.y);
    atomicAdd(&g_fc1[bb * F1c + j4 + 2], a0.z + a1.z);
    atomicAdd(&g_fc1[bb * F1c + j4 + 3], a0.w + a1.w);
}

__global__ void fc2_kernel(const float* __restrict__ w) {
    __shared__ float ts[F1c / FC2KT];
    const int bb = blockIdx.x >> 2;
    const int kt = blockIdx.x & (FC2KT - 1);
    const int k0 = kt * (F1c / FC2KT);
    for (int k = threadIdx.x; k < F1c / FC2KT; k += 128)
        ts[k] = fmaxf(g_fc1[bb * F1c + k0 + k], 0.f);
    __syncthreads();
    const int j = threadIdx.x;
    float a0 = 0.f, a1 = 0.f;
    for (int k = 0; k < F1c / FC2KT; k += 2) {
        a0 = fmaf(ts[k],     w[(size_t)(k0 + k) * F2c + j],     a0);
        a1 = fmaf(ts[k + 1], w[(size_t)(k0 + k + 1) * F2c + j], a1);
    }
    atomicAdd(&g_fc2[bb * F2c + j], a0 + a1);
}

__global__ void fc3_kernel(const float* __restrict__ w,
                           const float* __restrict__ bias,
                           float* __restrict__ dout) {
    const int bb = threadIdx.x >> 5;
    const int lane = threadIdx.x & 31;
    float acc = 0.f;
    for (int k = lane; k < F2c; k += 32)
        acc += fmaxf(g_fc2[bb * F2c + k], 0.f) * w[k];
    for (int o = 16; o; o >>= 1) acc += __shfl_down_sync(0xffffffffu, acc, o);
    if (!lane) dout[OFF_PRED + bb] = acc + bias[0];
}

// ---------------- launch ----------------
extern "C" void kernel_launch(void* const* d_in, const int* in_sizes, int n_in,
                              void* d_out, int out_size) {
    const float* x        = (const float*)d_in[0];
    const float* W1       = (const float*)d_in[1];
    const float* att_src1 = (const float*)d_in[2];
    const float* att_dst1 = (const float*)d_in[3];
    const float* b1       = (const float*)d_in[4];
    const float* W2       = (const float*)d_in[5];
    const float* att_src2 = (const float*)d_in[6];
    const float* att_dst2 = (const float*)d_in[7];
    const float* b2       = (const float*)d_in[8];
    const float* pw1      = (const float*)d_in[9];
    const float* pb1      = (const float*)d_in[10];
    const float* pw2      = (const float*)d_in[11];
    const float* pb2      = (const float*)d_in[12];
    const float* ln_w     = (const float*)d_in[13];
    const float* ln_b     = (const float*)d_in[14];
    const float* sex_emb  = (const float*)d_in[15];
    const float* mut_emb  = (const float*)d_in[16];
    const float* age_w    = (const float*)d_in[17];
    const float* age_b    = (const float*)d_in[18];
    const float* fw1      = (const float*)d_in[19];
    const float* fb1      = (const float*)d_in[20];
    const float* fw2      = (const float*)d_in[21];
    const float* fb2      = (const float*)d_in[22];
    const float* fw3      = (const float*)d_in[23];
    const float* fb3      = (const float*)d_in[24];
    const float* age      = (const float*)d_in[25];
    const int*   ei       = (const int*)d_in[26];
    const int*   sex      = (const int*)d_in[27];
    const int*   mut      = (const int*)d_in[28];

    const int Eb = in_sizes[26] / 2;
    const int Et = Eb + Nc;
    float* out = (float*)d_out;
    (void)n_in; (void)out_size;

    const int egrid = (Et + 255) / 256;
    const dim3 ggrid(Nc / 64, HCc / 64);

    // launch order: gemm_tc<FINc> in slot 4 (ncu capture)
    setup_kernel<<<4290, 256>>>(x, sex_emb, mut_emb, age_w, age_b, age,
                                sex, mut, fb1, fb2);                       // 1
    csr_count_kernel<<<egrid, 256>>>(ei, Eb, Et);                          // 2
    wa_all_kernel<<<6, 256>>>(W1, att_src1, att_dst1, W2, att_src2, att_dst2); // 3
    gemm_tc_kernel<FINc><<<ggrid, 256>>>(x, W1, 0);                        // 4 <- profiled
    att_logits_kernel<FINc><<<Nc / 8, 256>>>(x, 0);                        // 5
    scan_kernel<<<1, 1024>>>();                                            // 6
    csr_fill_kernel<<<egrid, 256>>>(ei, Eb, Et);                           // 7
    gat_agg_kernel<<<Nc / 4, 256>>>(b1, pw1, pb1, Bc * NNc);               // 8

    gemm_tc_kernel<HCc><<<ggrid, 256>>>(nullptr, W2, 1);
    att_logits_kernel<HCc><<<Nc / 8, 256>>>(nullptr, 1);
    gat_agg_kernel<<<Nc / 4, 256>>>(b2, pw2, pb2, 2 * Bc * NNc);

    // ---- head ----
    ln_kernel<<<3 * Bc, 256>>>(ln_w, ln_b, out);
    fc1_kernel<<<Bc * FC1KT, 128>>>(fw1);
    fc2_kernel<<<Bc * FC2KT, 128>>>(fw2);
    fc3_kernel<<<1, Bc * 32>>>(fw3, fb3, out);
}

// round 15
// speedup vs baseline: 1.1801x; 1.1290x over previous
#include <cuda_runtime.h>
#include <cuda_bf16.h>

// ---------------- problem constants ----------------
#define Bc    16
#define NNc   2000
#define Nc    (Bc * NNc)        // 32000 nodes
#define FINc  128
#define Hc    4
#define Cc    64
#define HCc   256
#define EMAXT 480000
#define FCINc (6 * NNc)         // 12000
#define F1c   512
#define F2c   128
#define FC1KT 16
#define FC2KT 4
#define SP    17                // gemm smem row stride (R10 best config)

// output layout (flattened tuple: pred, x0, x1, x2, ms)
#define OFF_PRED 0
#define OFF_X0   16
#define OFF_X1   (OFF_X0 + Bc * NNc)
#define OFF_X2   (OFF_X1 + Bc * NNc)
#define OFF_MS   (OFF_X2 + Bc * NNc)

// ---------------- device scratch ----------------
__device__ float g_hin[Nc * HCc];
__device__ float g_h[Nc * HCc];
__device__ float g_as[Nc * Hc];
__device__ float g_ad[Nc * Hc];
__device__ int   g_cnt[Nc];
__device__ int   g_rowp[Nc + 1];
__device__ int   g_cur[Nc];
__device__ int   g_csrc[EMAXT];
__device__ float g_x[3 * Bc * NNc];
__device__ float g_t[Bc * FCINc];
__device__ float g_fc1[Bc * F1c];
__device__ float g_fc2[Bc * F2c];

// ---------------- bf16 split helpers ----------------
__device__ __forceinline__ void bsplit2(float x0, float x1,
                                        unsigned& h, unsigned& l) {
    const __nv_bfloat16 h0 = __float2bfloat16(x0);
    const __nv_bfloat16 h1 = __float2bfloat16(x1);
    const __nv_bfloat16 l0 = __float2bfloat16(x0 - __bfloat162float(h0));
    const __nv_bfloat16 l1 = __float2bfloat16(x1 - __bfloat162float(h1));
    h = (unsigned)__bfloat16_as_ushort(h0) |
        ((unsigned)__bfloat16_as_ushort(h1) << 16);
    l = (unsigned)__bfloat16_as_ushort(l0) |
        ((unsigned)__bfloat16_as_ushort(l1) << 16);
}

__device__ __forceinline__ void mma16(float* d,
                                      unsigned a0, unsigned a1,
                                      unsigned a2, unsigned a3,
                                      unsigned b0, unsigned b1) {
    asm volatile(
        "mma.sync.aligned.m16n8k16.row.col.f32.bf16.bf16.f32 "
        "{%0,%1,%2,%3}, {%4,%5,%6,%7}, {%8,%9}, {%0,%1,%2,%3};"
        : "+f"(d[0]), "+f"(d[1]), "+f"(d[2]), "+f"(d[3])
        : "r"(a0), "r"(a1), "r"(a2), "r"(a3), "r"(b0), "r"(b1));
}

// ---------------- fused setup: x0_mean + zero_cnt + demo + fc init --------
__global__ void __launch_bounds__(256)
setup_kernel(const float* __restrict__ x,
             const float* __restrict__ sex_emb,
             const float* __restrict__ mut_emb,
             const float* __restrict__ age_w,
             const float* __restrict__ age_b,
             const float* __restrict__ age,
             const int* __restrict__ sex,
             const int* __restrict__ mut,
             const float* __restrict__ fb1,
             const float* __restrict__ fb2) {
    const int b = blockIdx.x;
    if (b < 4000) {                       // x0_mean: warp per node
        const int warp = b * 8 + (threadIdx.x >> 5);
        const int lane = threadIdx.x & 31;
        const float4 v =
            reinterpret_cast<const float4*>(x + (size_t)warp * FINc)[lane];
        float s = v.x + v.y + v.z + v.w;
        for (int o = 16; o; o >>= 1) s += __shfl_down_sync(0xffffffffu, s, o);
        if (!lane) g_x[warp] = s * (1.0f / FINc);
    } else if (b < 4125) {                // zero_cnt
        const int i = (b - 4000) * 256 + threadIdx.x;
        if (i < Nc) g_cnt[i] = 0;
    } else if (b < 4250) {                // demo
        const int i = (b - 4125) * 256 + threadIdx.x;
        if (i < Bc * NNc) {
            const int bb = i / NNc, i2 = i % NNc;
            g_t[bb * FCINc + i2]           = sex_emb[sex[bb] * NNc + i2];
            g_t[bb * FCINc + NNc + i2]     = mut_emb[mut[bb] * NNc + i2];
            g_t[bb * FCINc + 2 * NNc + i2] = fmaf(age[bb], age_w[i2], age_b[i2]);
        }
    } else if (b < 4282) {                // fc1_init
        const int i = (b - 4250) * 256 + threadIdx.x;
        if (i < Bc * F1c) g_fc1[i] = fb1[i & (F1c - 1)];
    } else {                              // fc2_init
        const int i = (b - 4282) * 256 + threadIdx.x;
        if (i < Bc * F2c) g_fc2[i] = fb2[i & (F2c - 1)];
    }
}

// ---------------- CSR build ----------------
__global__ void csr_count_kernel(const int* __restrict__ ei, int Eb, int Et) {
    const int e = blockIdx.x * blockDim.x + threadIdx.x;
    if (e >= Et) return;
    const int d = (e < Eb) ? ei[Eb + e] : (e - Eb);
    atomicAdd(&g_cnt[d], 1);
}

__global__ void scan_kernel() {
    __shared__ int partial[1024];
    const int T = 1024, CH = (Nc + T - 1) / T;
    const int t = threadIdx.x;
    const int base = t * CH;
    int s = 0;
    for (int i = 0; i < CH; ++i) {
        const int idx = base + i;
        if (idx < Nc) s += g_cnt[idx];
    }
    partial[t] = s;
    __syncthreads();
    for (int off = 1; off < T; off <<= 1) {
        int v = (t >= off) ? partial[t - off] : 0;
        __syncthreads();
        partial[t] += v;
        __syncthreads();
    }
    int run = t ? partial[t - 1] : 0;
    for (int i = 0; i < CH; ++i) {
        const int idx = base + i;
        if (idx < Nc) {
            g_rowp[idx] = run;
            g_cur[idx]  = run;
            run += g_cnt[idx];
        }
    }
    if (t == T - 1) g_rowp[Nc] = run;
}

__global__ void csr_fill_kernel(const int* __restrict__ ei, int Eb, int Et) {
    const int e = blockIdx.x * blockDim.x + threadIdx.x;
    if (e >= Et) return;
    int s, d;
    if (e < Eb) { s = ei[e]; d = ei[Eb + e]; }
    else        { s = e - Eb; d = s; }
    const int p = atomicAdd(&g_cur[d], 1);
    g_csrc[p] = s;
}

// ---------------- tensor-core node GEMM + fused attention logits ----------
// hin = X @ W (bf16 3-term split, R10 config). Each block owns rows
// [n0,n0+64) x head h = blockIdx.y (64 cols), so logits
// a_s[n,h] = sum_c d[n,c]*attS[h*64+c] are computed exactly from the fp32
// accumulators with NO atomics and written directly to g_as/g_ad.
template <int K>
__global__ void __launch_bounds__(256)
gemm_tc_kernel(const float* __restrict__ X, const float* __restrict__ W,
               const float* __restrict__ attS, const float* __restrict__ attD,
               int use_gh) {
    __shared__ unsigned xhi[64][SP], xlo[64][SP];
    __shared__ unsigned wh[64][SP],  wl[64][SP];
    __shared__ float s_ps[64], s_pd[64];
    const float* Xr = use_gh ? g_h : X;
    const int n0 = blockIdx.x * 64;
    const int c0 = blockIdx.y * 64;
    const int tid = threadIdx.x;
    const int warp = tid >> 5, lane = tid & 31;
    const int g = lane >> 2, t4 = lane & 3;
    const int rw = (warp & 3) * 16;
    const int cw = (warp >> 2) * 32;

    float d[4][4];
#pragma unroll
    for (int t = 0; t < 4; ++t)
#pragma unroll
        for (int i = 0; i < 4; ++i) d[t][i] = 0.f;

    for (int kc = 0; kc < K; kc += 32) {
#pragma unroll
        for (int p = 0; p < 2; ++p) {
            const int idx = tid + p * 256;
            const int r = idx >> 3, q = idx & 7;
            const float4 v = *reinterpret_cast<const float4*>(
                &Xr[(size_t)(n0 + r) * K + kc + q * 4]);
            bsplit2(v.x, v.y, xhi[r][q * 2],     xlo[r][q * 2]);
            bsplit2(v.z, v.w, xhi[r][q * 2 + 1], xlo[r][q * 2 + 1]);
        }
        {
            const int k2 = tid >> 4, n4 = tid & 15;
            const float* wp = &W[(size_t)(kc + 2 * k2) * HCc + c0 + n4 * 4];
            const float4 v0 = *reinterpret_cast<const float4*>(wp);
            const float4 v1 = *reinterpret_cast<const float4*>(wp + HCc);
            bsplit2(v0.x, v1.x, wh[n4 * 4 + 0][k2], wl[n4 * 4 + 0][k2]);
            bsplit2(v0.y, v1.y, wh[n4 * 4 + 1][k2], wl[n4 * 4 + 1][k2]);
            bsplit2(v0.z, v1.z, wh[n4 * 4 + 2][k2], wl[n4 * 4 + 2][k2]);
            bsplit2(v0.w, v1.w, wh[n4 * 4 + 3][k2], wl[n4 * 4 + 3][k2]);
        }
        __syncthreads();

#pragma unroll
        for (int ks2 = 0; ks2 < 16; ks2 += 8) {
            const unsigned a0h = xhi[rw + g][ks2 + t4];
            const unsigned a1h = xhi[rw + g + 8][ks2 + t4];
            const unsigned a2h = xhi[rw + g][ks2 + 4 + t4];
            const unsigned a3h = xhi[rw + g + 8][ks2 + 4 + t4];
            const unsigned a0l = xlo[rw + g][ks2 + t4];
            const unsigned a1l = xlo[rw + g + 8][ks2 + t4];
            const unsigned a2l = xlo[rw + g][ks2 + 4 + t4];
            const unsigned a3l = xlo[rw + g + 8][ks2 + 4 + t4];
#pragma unroll
            for (int t = 0; t < 4; ++t) {
                const int bn = cw + t * 8 + g;
                const unsigned b0h = wh[bn][ks2 + t4];
                const unsigned b1h = wh[bn][ks2 + 4 + t4];
                const unsigned b0l = wl[bn][ks2 + t4];
                const unsigned b1l = wl[bn][ks2 + 4 + t4];
                mma16(d[t], a0h, a1h, a2h, a3h, b0h, b1h);
                mma16(d[t], a0h, a1h, a2h, a3h, b0l, b1l);
                mma16(d[t], a0l, a1l, a2l, a3l, b0h, b1h);
            }
        }
        __syncthreads();
    }

    const int r  = n0 + rw + g;
    const int cc = c0 + cw + t4 * 2;
#pragma unroll
    for (int t = 0; t < 4; ++t) {
        *reinterpret_cast<float2*>(&g_hin[(size_t)r * HCc + cc + t * 8]) =
            make_float2(d[t][0], d[t][1]);
        *reinterpret_cast<float2*>(&g_hin[(size_t)(r + 8) * HCc + cc + t * 8]) =
            make_float2(d[t][2], d[t][3]);
    }

    // ---- fused logits epilogue: head h = blockIdx.y ----
    const int h = blockIdx.y;
    float ps0 = 0.f, pd0 = 0.f, ps1 = 0.f, pd1 = 0.f;
#pragma unroll
    for (int t = 0; t < 4; ++t) {
        const int c = cc + t * 8;
        const float sa0 = attS[c], sa1 = attS[c + 1];
        const float da0 = attD[c], da1 = attD[c + 1];
        ps0 = fmaf(d[t][0], sa0, fmaf(d[t][1], sa1, ps0));
        pd0 = fmaf(d[t][0], da0, fmaf(d[t][1], da1, pd0));
        ps1 = fmaf(d[t][2], sa0, fmaf(d[t][3], sa1, ps1));
        pd1 = fmaf(d[t][2], da0, fmaf(d[t][3], da1, pd1));
    }
#pragma unroll
    for (int o = 1; o < 4; o <<= 1) {
        ps0 += __shfl_xor_sync(0xffffffffu, ps0, o);
        pd0 += __shfl_xor_sync(0xffffffffu, pd0, o);
        ps1 += __shfl_xor_sync(0xffffffffu, ps1, o);
        pd1 += __shfl_xor_sync(0xffffffffu, pd1, o);
    }
    if (cw == 0 && t4 == 0) {
        s_ps[rw + g]     = ps0; s_pd[rw + g]     = pd0;
        s_ps[rw + g + 8] = ps1; s_pd[rw + g + 8] = pd1;
    }
    __syncthreads();
    if (cw == 32 && t4 == 0) {
        const int r0 = rw + g, r1 = rw + g + 8;
        g_as[(n0 + r0) * Hc + h] = ps0 + s_ps[r0];
        g_ad[(n0 + r0) * Hc + h] = pd0 + s_pd[r0];
        g_as[(n0 + r1) * Hc + h] = ps1 + s_ps[r1];
        g_ad[(n0 + r1) * Hc + h] = pd1 + s_pd[r1];
    }
}

// ---------------- fused GAT aggregation: 2 warps per dst node -------------
__device__ __forceinline__ float leaky02(float a) {
    return a > 0.f ? a : 0.2f * a;
}

__global__ void __launch_bounds__(256)
gat_agg_kernel(const float* __restrict__ bias,
               const float* __restrict__ pw,
               const float* __restrict__ pb,
               int xoff) {
    const int wip  = threadIdx.x >> 5;    // 0..7
    const int lane = threadIdx.x & 31;
    const int n    = blockIdx.x * 4 + (wip >> 1);
    const int half = wip & 1;
    __shared__ float s_w[8][32][4];   // UNNORMALIZED exp weights (per warp)
    __shared__ int   s_src[8][32];
    __shared__ float s_p[8];

    const int beg = g_rowp[n], end = g_rowp[n + 1];
    const int deg = end - beg;
    const float4 ad = *reinterpret_cast<const float4*>(&g_ad[n * Hc]);

    float4 sm;
    if (deg <= 32) {
        float4 w = make_float4(0.f, 0.f, 0.f, 0.f);
        if (lane < deg) {
            const int s = g_csrc[beg + lane];
            s_src[wip][lane] = s;
            const float4 as = *reinterpret_cast<const float4*>(&g_as[s * Hc]);
            w.x = __expf(leaky02(as.x + ad.x));
            w.y = __expf(leaky02(as.y + ad.y));
            w.z = __expf(leaky02(as.z + ad.z));
            w.w = __expf(leaky02(as.w + ad.w));
            *reinterpret_cast<float4*>(&s_w[wip][lane][0]) = w;
        }
        sm = w;
#pragma unroll
        for (int o = 16; o; o >>= 1) {
            sm.x += __shfl_xor_sync(0xffffffffu, sm.x, o);
            sm.y += __shfl_xor_sync(0xffffffffu, sm.y, o);
            sm.z += __shfl_xor_sync(0xffffffffu, sm.z, o);
            sm.w += __shfl_xor_sync(0xffffffffu, sm.w, o);
        }
    } else {
        sm = make_float4(0.f, 0.f, 0.f, 0.f);
        for (int e = beg + lane; e < end; e += 32) {
            const int s = g_csrc[e];
            const float4 as = *reinterpret_cast<const float4*>(&g_as[s * Hc]);
            sm.x += __expf(leaky02(as.x + ad.x));
            sm.y += __expf(leaky02(as.y + ad.y));
            sm.z += __expf(leaky02(as.z + ad.z));
            sm.w += __expf(leaky02(as.w + ad.w));
        }
#pragma unroll
        for (int o = 16; o; o >>= 1) {
            sm.x += __shfl_xor_sync(0xffffffffu, sm.x, o);
            sm.y += __shfl_xor_sync(0xffffffffu, sm.y, o);
            sm.z += __shfl_xor_sync(0xffffffffu, sm.z, o);
            sm.w += __shfl_xor_sync(0xffffffffu, sm.w, o);
        }
    }
    const float4 inv = make_float4(1.f / (sm.x + 1e-16f), 1.f / (sm.y + 1e-16f),
                                   1.f / (sm.z + 1e-16f), 1.f / (sm.w + 1e-16f));

    const int c0 = half * 128 + lane * 4;
    const int h  = c0 >> 6;
    const float invh = reinterpret_cast<const float*>(&inv)[h];
    float4 acc = make_float4(0.f, 0.f, 0.f, 0.f);

    for (int cb = beg; cb < end; cb += 32) {
        const int ne = min(32, end - cb);
        if (cb != beg || deg > 32) {
            __syncwarp();
            if (lane < ne) {
                const int s = g_csrc[cb + lane];
                s_src[wip][lane] = s;
                const float4 as = *reinterpret_cast<const float4*>(&g_as[s * Hc]);
                float4 w;
                w.x = __expf(leaky02(as.x + ad.x));
                w.y = __expf(leaky02(as.y + ad.y));
                w.z = __expf(leaky02(as.z + ad.z));
                w.w = __expf(leaky02(as.w + ad.w));
                *reinterpret_cast<float4*>(&s_w[wip][lane][0]) = w;
            }
        }
        __syncwarp();
        int e = 0;
#pragma unroll 4
        for (; e + 4 <= ne; e += 4) {
            const int   s0i = s_src[wip][e];
            const int   s1i = s_src[wip][e + 1];
            const int   s2i = s_src[wip][e + 2];
            const int   s3i = s_src[wip][e + 3];
            const float w0 = s_w[wip][e][h]     * invh;
            const float w1 = s_w[wip][e + 1][h] * invh;
            const float w2 = s_w[wip][e + 2][h] * invh;
            const float w3 = s_w[wip][e + 3][h] * invh;
            const float4 v0 = *reinterpret_cast<const float4*>(&g_hin[(size_t)s0i * HCc + c0]);
            const float4 v1 = *reinterpret_cast<const float4*>(&g_hin[(size_t)s1i * HCc + c0]);
            const float4 v2 = *reinterpret_cast<const float4*>(&g_hin[(size_t)s2i * HCc + c0]);
            const float4 v3 = *reinterpret_cast<const float4*>(&g_hin[(size_t)s3i * HCc + c0]);
            acc.x = fmaf(w0, v0.x, acc.x); acc.y = fmaf(w0, v0.y, acc.y);
            acc.z = fmaf(w0, v0.z, acc.z); acc.w = fmaf(w0, v0.w, acc.w);
            acc.x = fmaf(w1, v1.x, acc.x); acc.y = fmaf(w1, v1.y, acc.y);
            acc.z = fmaf(w1, v1.z, acc.z); acc.w = fmaf(w1, v1.w, acc.w);
            acc.x = fmaf(w2, v2.x, acc.x); acc.y = fmaf(w2, v2.y, acc.y);
            acc.z = fmaf(w2, v2.z, acc.z); acc.w = fmaf(w2, v2.w, acc.w);
            acc.x = fmaf(w3, v3.x, acc.x); acc.y = fmaf(w3, v3.y, acc.y);
            acc.z = fmaf(w3, v3.z, acc.z); acc.w = fmaf(w3, v3.w, acc.w);
        }
        for (; e < ne; ++e) {
            const int   s = s_src[wip][e];
            const float w = s_w[wip][e][h] * invh;
            const float4 v = *reinterpret_cast<const float4*>(&g_hin[(size_t)s * HCc + c0]);
            acc.x = fmaf(w, v.x, acc.x); acc.y = fmaf(w, v.y, acc.y);
            acc.z = fmaf(w, v.z, acc.z); acc.w = fmaf(w, v.w, acc.w);
        }
    }

    const float4 bv = *reinterpret_cast<const float4*>(&bias[c0]);
    float4 r;
    r.x = fmaxf(acc.x + bv.x, 0.f); r.y = fmaxf(acc.y + bv.y, 0.f);
    r.z = fmaxf(acc.z + bv.z, 0.f); r.w = fmaxf(acc.w + bv.w, 0.f);
    *reinterpret_cast<float4*>(&g_h[(size_t)n * HCc + c0]) = r;

    const float4 pv = *reinterpret_cast<const float4*>(&pw[c0]);
    float p = r.x * pv.x + r.y * pv.y + r.z * pv.z + r.w * pv.w;
#pragma unroll
    for (int o = 16; o; o >>= 1) p += __shfl_xor_sync(0xffffffffu, p, o);
    if (!lane) s_p[wip] = p;
    __syncthreads();
    if (!half && !lane) g_x[xoff + n] = s_p[wip] + s_p[wip + 1] + pb[0];
}

// ---------------- head ----------------
__global__ void ln_kernel(const float* __restrict__ w,
                          const float* __restrict__ b,
                          float* __restrict__ dout) {
    const int a  = blockIdx.x / Bc;
    const int bb = blockIdx.x % Bc;
    const float* src = g_x + a * Bc * NNc + bb * NNc;
    __shared__ float rs[256], rq[256];
    float s = 0.f, q = 0.f;
    for (int i = threadIdx.x; i < NNc; i += 256) {
        const float v = src[i];
        s += v; q += v * v;
    }
    rs[threadIdx.x] = s; rq[threadIdx.x] = q;
    __syncthreads();
    for (int o = 128; o; o >>= 1) {
        if (threadIdx.x < o) {
            rs[threadIdx.x] += rs[threadIdx.x + o];
            rq[threadIdx.x] += rq[threadIdx.x + o];
        }
        __syncthreads();
    }
    const float mu  = rs[0] * (1.0f / NNc);
    const float var = rq[0] * (1.0f / NNc) - mu * mu;
    const float inv = rsqrtf(var + 1e-5f);
    for (int i = threadIdx.x; i < NNc; i += 256) {
        const float y = (src[i] - mu) * inv * w[i] + b[i];
        dout[OFF_X0 + a * Bc * NNc + bb * NNc + i] = y;
        dout[OFF_MS + bb * 3 * NNc + a * NNc + i] = y;
        g_t[bb * FCINc + 3 * NNc + a * NNc + i]   = y;
    }
}

__global__ void fc1_kernel(const float* __restrict__ w) {
    __shared__ float ts[FCINc / FC1KT];
    const int bb = blockIdx.x >> 4;
    const int kt = blockIdx.x & (FC1KT - 1);
    const int k0 = kt * (FCINc / FC1KT);
    for (int k = threadIdx.x; k < FCINc / FC1KT; k += 128)
        ts[k] = g_t[bb * FCINc + k0 + k];
    __syncthreads();
    const int j4 = threadIdx.x * 4;
    float4 a0 = make_float4(0, 0, 0, 0), a1 = make_float4(0, 0, 0, 0);
    for (int k = 0; k < FCINc / FC1KT; k += 2) {
        const float t0 = ts[k], t1 = ts[k + 1];
        const float4 w0 = *reinterpret_cast<const float4*>(&w[(size_t)(k0 + k) * F1c + j4]);
        const float4 w1 = *reinterpret_cast<const float4*>(&w[(size_t)(k0 + k + 1) * F1c + j4]);
        a0.x = fmaf(t0, w0.x, a0.x); a1.x = fmaf(t1, w1.x, a1.x);
        a0.y = fmaf(t0, w0.y, a0.y); a1.y = fmaf(t1, w1.y, a1.y);
        a0.z = fmaf(t0, w0.z, a0.z); a1.z = fmaf(t1, w1.z, a1.z);
        a0.w = fmaf(t0, w0.w, a0.w); a1.w = fmaf(t1, w1.w, a1.w);
    }
    atomicAdd(&g_fc1[bb * F1c + j4 + 0], a0.x + a1.x);
    atomicAdd(&g_fc1[bb * F1c + j4 + 1], a0.y + a1.y);
    atomicAdd(&g_fc1[bb * F1c + j4 + 2], a0.z + a1.z);
    atomicAdd(&g_fc1[bb * F1c + j4 + 3], a0.w + a1.w);
}

__global__ void fc2_kernel(const float* __restrict__ w) {
    __shared__ float ts[F1c / FC2KT];
    const int bb = blockIdx.x >> 2;
    const int kt = blockIdx.x & (FC2KT - 1);
    const int k0 = kt * (F1c / FC2KT);
    for (int k = threadIdx.x; k < F1c / FC2KT; k += 128)
        ts[k] = fmaxf(g_fc1[bb * F1c + k0 + k], 0.f);
    __syncthreads();
    const int j = threadIdx.x;
    float a0 = 0.f, a1 = 0.f;
    for (int k = 0; k < F1c / FC2KT; k += 2) {
        a0 = fmaf(ts[k],     w[(size_t)(k0 + k) * F2c + j],     a0);
        a1 = fmaf(ts[k + 1], w[(size_t)(k0 + k + 1) * F2c + j], a1);
    }
    atomicAdd(&g_fc2[bb * F2c + j], a0 + a1);
}

__global__ void fc3_kernel(const float* __restrict__ w,
                           const float* __restrict__ bias,
                           float* __restrict__ dout) {
    const int bb = threadIdx.x >> 5;
    const int lane = threadIdx.x & 31;
    float acc = 0.f;
    for (int k = lane; k < F2c; k += 32)
        acc += fmaxf(g_fc2[bb * F2c + k], 0.f) * w[k];
    for (int o = 16; o; o >>= 1) acc += __shfl_down_sync(0xffffffffu, acc, o);
    if (!lane) dout[OFF_PRED + bb] = acc + bias[0];
}

// ---------------- launch ----------------
extern "C" void kernel_launch(void* const* d_in, const int* in_sizes, int n_in,
                              void* d_out, int out_size) {
    const float* x        = (const float*)d_in[0];
    const float* W1       = (const float*)d_in[1];
    const float* att_src1 = (const float*)d_in[2];
    const float* att_dst1 = (const float*)d_in[3];
    const float* b1       = (const float*)d_in[4];
    const float* W2       = (const float*)d_in[5];
    const float* att_src2 = (const float*)d_in[6];
    const float* att_dst2 = (const float*)d_in[7];
    const float* b2       = (const float*)d_in[8];
    const float* pw1      = (const float*)d_in[9];
    const float* pb1      = (const float*)d_in[10];
    const float* pw2      = (const float*)d_in[11];
    const float* pb2      = (const float*)d_in[12];
    const float* ln_w     = (const float*)d_in[13];
    const float* ln_b     = (const float*)d_in[14];
    const float* sex_emb  = (const float*)d_in[15];
    const float* mut_emb  = (const float*)d_in[16];
    const float* age_w    = (const float*)d_in[17];
    const float* age_b    = (const float*)d_in[18];
    const float* fw1      = (const float*)d_in[19];
    const float* fb1      = (const float*)d_in[20];
    const float* fw2      = (const float*)d_in[21];
    const float* fb2      = (const float*)d_in[22];
    const float* fw3      = (const float*)d_in[23];
    const float* fb3      = (const float*)d_in[24];
    const float* age      = (const float*)d_in[25];
    const int*   ei       = (const int*)d_in[26];
    const int*   sex      = (const int*)d_in[27];
    const int*   mut      = (const int*)d_in[28];

    const int Eb = in_sizes[26] / 2;
    const int Et = Eb + Nc;
    float* out = (float*)d_out;
    (void)n_in; (void)out_size;

    const int egrid = (Et + 255) / 256;
    const dim3 ggrid(Nc / 64, HCc / 64);

    // launch order: gemm_tc<FINc> in slot 4 (ncu capture)
    setup_kernel<<<4290, 256>>>(x, sex_emb, mut_emb, age_w, age_b, age,
                                sex, mut, fb1, fb2);                       // 1
    csr_count_kernel<<<egrid, 256>>>(ei, Eb, Et);                          // 2
    scan_kernel<<<1, 1024>>>();                                            // 3
    gemm_tc_kernel<FINc><<<ggrid, 256>>>(x, W1, att_src1, att_dst1, 0);    // 4 <- profiled
    csr_fill_kernel<<<egrid, 256>>>(ei, Eb, Et);                           // 5
    gat_agg_kernel<<<Nc / 4, 256>>>(b1, pw1, pb1, Bc * NNc);               // 6

    gemm_tc_kernel<HCc><<<ggrid, 256>>>(nullptr, W2, att_src2, att_dst2, 1); // 7
    gat_agg_kernel<<<Nc / 4, 256>>>(b2, pw2, pb2, 2 * Bc * NNc);           // 8

    // ---- head ----
    ln_kernel<<<3 * Bc, 256>>>(ln_w, ln_b, out);                           // 9
    fc1_kernel<<<Bc * FC1KT, 128>>>(fw1);                                  // 10
    fc2_kernel<<<Bc * FC2KT, 128>>>(fw2);                                  // 11
    fc3_kernel<<<1, Bc * 32>>>(fw3, fb3, out);                             // 12
}